// round 5
// baseline (speedup 1.0000x reference)
#include <cuda_runtime.h>
#include <math.h>
#include <stdint.h>

// Problem constants (fixed by setup_inputs)
#define BATCH 2
#define TSEQ  2048
#define DMOD  2048
#define NHEAD 16
#define DHEAD 128
#define MROWS (BATCH * TSEQ)        // 4096
#define QKVN  (3 * DMOD)            // 6144

// ---------------------------------------------------------------------------
// Scratch (static device globals; no runtime allocation)
// ---------------------------------------------------------------------------
__device__ float g_qkv[(size_t)MROWS * QKVN];
__device__ float g_q[(size_t)BATCH * NHEAD * TSEQ * DHEAD];
__device__ float g_k[(size_t)BATCH * NHEAD * TSEQ * DHEAD];
__device__ float g_v[(size_t)BATCH * NHEAD * TSEQ * DHEAD];
__device__ float g_o[(size_t)BATCH * NHEAD * TSEQ * DHEAD];
__device__ float g_g[(size_t)MROWS * DMOD];
// tf32-rounded copies of inputs
__device__ float g_xr[(size_t)MROWS * DMOD];
__device__ float g_wqkvr[(size_t)DMOD * QKVN];
__device__ float g_wgater[(size_t)DMOD * DMOD];
__device__ float g_woutr[(size_t)DMOD * DMOD];
// RoPE table: [t][j] -> (cos, sin), j = 0..63
__device__ float2 g_rope[(size_t)TSEQ * 64];

// ---------------------------------------------------------------------------
// Helpers
// ---------------------------------------------------------------------------
__device__ __forceinline__ uint32_t f2tf(float x) {
    uint32_t r;
    asm("cvt.rna.tf32.f32 %0, %1;" : "=r"(r) : "f"(x));
    return r;
}

__device__ __forceinline__ void mma_tf32(float* c, const uint32_t* a, const uint32_t* b) {
    asm volatile(
        "mma.sync.aligned.m16n8k8.row.col.f32.tf32.tf32.f32 "
        "{%0,%1,%2,%3},{%4,%5,%6,%7},{%8,%9},{%0,%1,%2,%3};\n"
        : "+f"(c[0]), "+f"(c[1]), "+f"(c[2]), "+f"(c[3])
        : "r"(a[0]), "r"(a[1]), "r"(a[2]), "r"(a[3]), "r"(b[0]), "r"(b[1]));
}

__device__ __forceinline__ void cpa16(void* dst, const void* src) {
    uint32_t d = (uint32_t)__cvta_generic_to_shared(dst);
    asm volatile("cp.async.cg.shared.global [%0], [%1], 16;" :: "r"(d), "l"(src));
}
#define CP_COMMIT() asm volatile("cp.async.commit_group;")
#define CP_WAIT0()  asm volatile("cp.async.wait_group 0;")
#define CP_WAIT1()  asm volatile("cp.async.wait_group 1;")

// ---------------------------------------------------------------------------
// RoPE table precompute (double precision, once): 2048 x 64 (cos, sin)
// ---------------------------------------------------------------------------
__global__ void __launch_bounds__(256)
rope_table_kernel(float2* __restrict__ tab)
{
    int idx = blockIdx.x * blockDim.x + threadIdx.x;
    if (idx < TSEQ * 64) {
        int t = idx >> 6;
        int j = idx & 63;
        double freq = exp(-((double)j / 64.0) * 9.210340371976184);  // ln(1e4)
        double ang = (double)t * freq;
        double sd, cd;
        sincos(ang, &sd, &cd);
        tab[idx] = make_float2((float)cd, (float)sd);
    }
}

// ---------------------------------------------------------------------------
// Elementwise tf32 rounding pass (float4 vectorized)
// ---------------------------------------------------------------------------
__global__ void __launch_bounds__(256)
tf32_round_kernel(const float* __restrict__ in, float* __restrict__ out, int n4)
{
    int i = blockIdx.x * blockDim.x + threadIdx.x;
    if (i < n4) {
        float4 v = ((const float4*)in)[i];
        v.x = __uint_as_float(f2tf(v.x));
        v.y = __uint_as_float(f2tf(v.y));
        v.z = __uint_as_float(f2tf(v.z));
        v.w = __uint_as_float(f2tf(v.w));
        ((float4*)out)[i] = v;
    }
}

// ---------------------------------------------------------------------------
// tf32 GEMM: C[M,N] = A[M,K] @ B[K,N] (A,B pre-rounded to tf32 values).
// BM=128, BN=256, BK=16, 3-stage cp.async, 256 threads, warp tile 64x64
// (warps 2x4). mode 0: plain; mode 1: sigmoid-gate epilogue.
// ---------------------------------------------------------------------------
#define BM 128
#define BN 256
#define BK 16
#define BKP (BK + 4)    // 20
#define BNP (BN + 8)    // 264
#define GST 3           // stages

#define AS(s, r, c) Ash[(size_t)(s) * BM * BKP + (r) * BKP + (c)]
#define BS(s, r, c) Bsh[(size_t)(s) * BK * BNP + (r) * BNP + (c)]

__global__ void __launch_bounds__(256, 1)
mm_tf32_kernel(const float* __restrict__ A, const float* __restrict__ B,
               float* __restrict__ C, int M, int N, int K,
               int mode, const float* __restrict__ bias,
               const float* __restrict__ gateO)
{
    extern __shared__ float gsm[];
    float* Ash = gsm;
    float* Bsh = gsm + GST * BM * BKP;

    const int bx = blockIdx.x, by = blockIdx.y;
    const int tid = threadIdx.x;
    const int lane = tid & 31;
    const int warp = tid >> 5;
    const int wm = warp >> 2;          // 0..1 -> M offset wm*64
    const int wn = warp & 3;           // 0..3 -> N offset wn*64
    const int g  = lane >> 2;          // 0..7
    const int tg = lane & 3;           // 0..3

    const float* Abase = A + (size_t)(by * BM) * K;
    const float* Bbase = B + (size_t)(bx * BN);

    float acc[4][8][4];
#pragma unroll
    for (int im = 0; im < 4; im++)
#pragma unroll
        for (int in = 0; in < 8; in++)
#pragma unroll
            for (int j = 0; j < 4; j++) acc[im][in][j] = 0.f;

    const int KT = K / BK;

    // loaders: A = 128x16 (512 f4, 2/thread), B = 16x256 (1024 f4, 4/thread)
#pragma unroll
    for (int s = 0; s < 2; s++) {
        const int k0 = s * BK;
#pragma unroll
        for (int p = 0; p < 2; p++) {
            int idx = tid + p * 256;
            int r = idx >> 2;
            int c4 = (idx & 3) << 2;
            cpa16(&AS(s, r, c4), Abase + (size_t)r * K + k0 + c4);
        }
#pragma unroll
        for (int p = 0; p < 4; p++) {
            int idx = tid + p * 256;
            int r = idx >> 6;
            int c4 = (idx & 63) << 2;
            cpa16(&BS(s, r, c4), Bbase + (size_t)(k0 + r) * N + c4);
        }
        CP_COMMIT();
    }

    for (int kt = 0; kt < KT; kt++) {
        const int cur = kt % GST;
        if (kt + 1 < KT) { CP_WAIT1(); } else { CP_WAIT0(); }
        __syncthreads();

        if (kt + 2 < KT) {
            const int nxt = (kt + 2) % GST;
            const int k0 = (kt + 2) * BK;
#pragma unroll
            for (int p = 0; p < 2; p++) {
                int idx = tid + p * 256;
                int r = idx >> 2;
                int c4 = (idx & 3) << 2;
                cpa16(&AS(nxt, r, c4), Abase + (size_t)r * K + k0 + c4);
            }
#pragma unroll
            for (int p = 0; p < 4; p++) {
                int idx = tid + p * 256;
                int r = idx >> 6;
                int c4 = (idx & 63) << 2;
                cpa16(&BS(nxt, r, c4), Bbase + (size_t)(k0 + r) * N + c4);
            }
            CP_COMMIT();
        }

#pragma unroll
        for (int ik = 0; ik < 2; ik++) {
            uint32_t afr[4][4];
#pragma unroll
            for (int im = 0; im < 4; im++) {
                int r = wm * 64 + im * 16 + g;
                int c = ik * 8 + tg;
                afr[im][0] = __float_as_uint(AS(cur, r, c));
                afr[im][1] = __float_as_uint(AS(cur, r + 8, c));
                afr[im][2] = __float_as_uint(AS(cur, r, c + 4));
                afr[im][3] = __float_as_uint(AS(cur, r + 8, c + 4));
            }
            uint32_t bfr[8][2];
#pragma unroll
            for (int in = 0; in < 8; in++) {
                int cc = wn * 64 + in * 8 + g;
                int rk = ik * 8 + tg;
                bfr[in][0] = __float_as_uint(BS(cur, rk, cc));
                bfr[in][1] = __float_as_uint(BS(cur, rk + 4, cc));
            }
#pragma unroll
            for (int im = 0; im < 4; im++)
#pragma unroll
                for (int in = 0; in < 8; in++)
                    mma_tf32(acc[im][in], afr[im], bfr[in]);
        }
    }

    if (mode == 0) {
#pragma unroll
        for (int im = 0; im < 4; im++) {
            int r = by * BM + wm * 64 + im * 16 + g;
#pragma unroll
            for (int in = 0; in < 8; in++) {
                int c = bx * BN + wn * 64 + in * 8 + 2 * tg;
                *(float2*)(C + (size_t)r * N + c) =
                    make_float2(acc[im][in][0], acc[im][in][1]);
                *(float2*)(C + (size_t)(r + 8) * N + c) =
                    make_float2(acc[im][in][2], acc[im][in][3]);
            }
        }
    } else {
#pragma unroll
        for (int im = 0; im < 4; im++) {
            int rbase = by * BM + wm * 64 + im * 16 + g;
#pragma unroll
            for (int in = 0; in < 8; in++) {
                int cbase = bx * BN + wn * 64 + in * 8 + 2 * tg;
#pragma unroll
                for (int e = 0; e < 4; e++) {
                    int r = rbase + (e >> 1) * 8;
                    int c = cbase + (e & 1);
                    int b = r >> 11;
                    int t = r & (TSEQ - 1);
                    float z = acc[im][in][e] + bias[c];
                    float gte = 1.f / (1.f + expf(-z));
                    int h = c >> 7;
                    int dd = c & (DHEAD - 1);
                    size_t oidx = (((size_t)(b * NHEAD + h)) * TSEQ + t) * DHEAD + dd;
                    C[(size_t)r * N + c] = __uint_as_float(f2tf(gte * gateO[oidx]));
                }
            }
        }
    }
}

// ---------------------------------------------------------------------------
// RMSNorm + RoPE for q,k (plus v permute); outputs tf32-rounded.
// Q is pre-scaled by 1/sqrt(d). RoPE angles from precomputed table.
// ---------------------------------------------------------------------------
__global__ void __launch_bounds__(128)
norm_rope_kernel(const float* __restrict__ qkv,
                 const float2* __restrict__ rtab,
                 float* __restrict__ Qo, float* __restrict__ Ko,
                 float* __restrict__ Vo)
{
    const int rid = blockIdx.x;
    const int t  = rid & (TSEQ - 1);
    const int bh = rid >> 11;
    const int b  = bh >> 4;
    const int h  = bh & (NHEAD - 1);
    const int i  = threadIdx.x;

    const float* row = qkv + ((size_t)(b * TSEQ + t)) * QKVN + h * DHEAD;
    float qv = row[i];
    float kv = row[DMOD + i];
    float vv = row[2 * DMOD + i];

    float q2 = qv * qv, k2 = kv * kv;
#pragma unroll
    for (int o = 16; o; o >>= 1) {
        q2 += __shfl_xor_sync(0xffffffffu, q2, o);
        k2 += __shfl_xor_sync(0xffffffffu, k2, o);
    }
    __shared__ float rq[4], rk[4];
    if ((i & 31) == 0) { rq[i >> 5] = q2; rk[i >> 5] = k2; }
    __syncthreads();
    float ssq = rq[0] + rq[1] + rq[2] + rq[3];
    float ssk = rk[0] + rk[1] + rk[2] + rk[3];
    float rnq = rsqrtf(ssq * (1.f / DHEAD) + 1e-6f);
    float rnk = rsqrtf(ssk * (1.f / DHEAD) + 1e-6f);

    __shared__ float sq[DHEAD], sk[DHEAD];
    sq[i] = qv * rnq;
    sk[i] = kv * rnk;
    __syncthreads();

    const int j = i & 63;
    float2 cs = rtab[(size_t)t * 64 + j];
    float c = cs.x, s = cs.y;

    float oq, ok;
    if (i < 64) {
        oq = sq[i] * c - sq[i + 64] * s;
        ok = sk[i] * c - sk[i + 64] * s;
    } else {
        oq = sq[i - 64] * s + sq[i] * c;
        ok = sk[i - 64] * s + sk[i] * c;
    }
    const float qscale = 0.08838834764831845f;  // 1/sqrt(128), folded into Q
    size_t oidx = ((size_t)bh * TSEQ + t) * DHEAD + i;
    Qo[oidx] = __uint_as_float(f2tf(oq * qscale));
    Ko[oidx] = __uint_as_float(f2tf(ok));
    Vo[oidx] = __uint_as_float(f2tf(vv));
}

// ---------------------------------------------------------------------------
// Flash attention (causal), tf32 mma. Br=128, Bc=64, 256 threads (8 warps),
// double-buffered cp.async K/V. Q staged into the K-buffer region (fragments
// move to registers before K/V streaming starts). Scale pre-folded into Q.
// ---------------------------------------------------------------------------
#define ABR 128
#define ABC 64
#define DP  132   // d + 4
#define PP  68    // Bc + 4
#define KTF (ABR / ABC)   // 2 kv-tiles per q-tile

#define FK_OFF 0
#define FV_OFF (2 * ABC * DP)
#define FP_OFF (FV_OFF + 2 * ABC * DP)
#define FSM_FLOATS (FP_OFF + ABR * PP)

__global__ void __launch_bounds__(256, 1)
flash_mma_kernel(const float* __restrict__ Qg, const float* __restrict__ Kg,
                 const float* __restrict__ Vg, float* __restrict__ Og)
{
    extern __shared__ float fsm[];
    float* Ps = fsm + FP_OFF;

    const int qt = (gridDim.x - 1) - blockIdx.x;   // heavy tiles first
    const int bh = blockIdx.y;
    const int tid  = threadIdx.x;
    const int lane = tid & 31;
    const int w    = tid >> 5;
    const int g    = lane >> 2;
    const int tg   = lane & 3;

    const float* Qb = Qg + (size_t)bh * TSEQ * DHEAD;
    const float* Kb = Kg + (size_t)bh * TSEQ * DHEAD;
    const float* Vb = Vg + (size_t)bh * TSEQ * DHEAD;

    const int ktmax = KTF * (qt + 1);

    // --- prologue: stage Q (128x128) into K region, move frags to registers
    {
        float* Qs = fsm;
#pragma unroll
        for (int p = 0; p < 16; p++) {
            int idx = tid + p * 256;
            int r = idx >> 5;
            int c = (idx & 31) << 2;
            cpa16(&Qs[r * DP + c], Qb + (size_t)(qt * ABR + r) * DHEAD + c);
        }
        CP_COMMIT();
        CP_WAIT0();
        __syncthreads();
    }

    uint32_t qf[16][4];
    {
        const float* Qs = fsm;
        int r = w * 16 + g;
#pragma unroll
        for (int ik = 0; ik < 16; ik++) {
            int c = ik * 8 + tg;
            qf[ik][0] = __float_as_uint(Qs[r * DP + c]);
            qf[ik][1] = __float_as_uint(Qs[(r + 8) * DP + c]);
            qf[ik][2] = __float_as_uint(Qs[r * DP + c + 4]);
            qf[ik][3] = __float_as_uint(Qs[(r + 8) * DP + c + 4]);
        }
    }
    __syncthreads();

    // prefetch kv tile 0 into buffer 0
    {
        float* ks = fsm + FK_OFF;
        float* vs = fsm + FV_OFF;
#pragma unroll
        for (int p = 0; p < 8; p++) {
            int idx = tid + p * 256;
            int r = idx >> 5;
            int c = (idx & 31) << 2;
            cpa16(&ks[r * DP + c], Kb + (size_t)r * DHEAD + c);
            cpa16(&vs[r * DP + c], Vb + (size_t)r * DHEAD + c);
        }
        CP_COMMIT();
    }

    float oacc[16][4];
#pragma unroll
    for (int in = 0; in < 16; in++)
#pragma unroll
        for (int j = 0; j < 4; j++) oacc[in][j] = 0.f;
    float m_i[2] = {-INFINITY, -INFINITY};
    float l_i[2] = {0.f, 0.f};

    const int rlo = qt * ABR + w * 16 + g;

    for (int kt = 0; kt < ktmax; kt++) {
        if (kt + 1 < ktmax) {
            int s = (kt + 1) & 1;
            const float* kp = Kb + (size_t)(kt + 1) * ABC * DHEAD;
            const float* vp = Vb + (size_t)(kt + 1) * ABC * DHEAD;
            float* ks = fsm + FK_OFF + s * ABC * DP;
            float* vs = fsm + FV_OFF + s * ABC * DP;
#pragma unroll
            for (int p = 0; p < 8; p++) {
                int idx = tid + p * 256;
                int r = idx >> 5;
                int c = (idx & 31) << 2;
                cpa16(&ks[r * DP + c], kp + (size_t)r * DHEAD + c);
                cpa16(&vs[r * DP + c], vp + (size_t)r * DHEAD + c);
            }
            CP_COMMIT();
            CP_WAIT1();
        } else {
            CP_WAIT0();
        }
        __syncthreads();

        const float* Ksc = fsm + FK_OFF + (kt & 1) * ABC * DP;
        const float* Vsc = fsm + FV_OFF + (kt & 1) * ABC * DP;

        // S = Q @ K^T  (warp: 16 x 64; 8 n-atoms)
        float sacc[8][4];
#pragma unroll
        for (int in = 0; in < 8; in++)
#pragma unroll
            for (int j = 0; j < 4; j++) sacc[in][j] = 0.f;

#pragma unroll
        for (int ik = 0; ik < 16; ik++) {
#pragma unroll
            for (int in = 0; in < 8; in++) {
                uint32_t bf[2];
                int srow = in * 8 + g;
                int dcol = ik * 8 + tg;
                bf[0] = __float_as_uint(Ksc[srow * DP + dcol]);
                bf[1] = __float_as_uint(Ksc[srow * DP + dcol + 4]);
                mma_tf32(sacc[in], qf[ik], bf);
            }
        }

        if (kt >= KTF * qt) {
#pragma unroll
            for (int in = 0; in < 8; in++) {
                int cbase = kt * ABC + in * 8 + 2 * tg;
#pragma unroll
                for (int j = 0; j < 4; j++) {
                    int cg = cbase + (j & 1);
                    int rg = rlo + (j >> 1) * 8;
                    if (cg > rg) sacc[in][j] = -INFINITY;
                }
            }
        }

        // online softmax per owned row
        float alpha[2];
#pragma unroll
        for (int rr = 0; rr < 2; rr++) {
            float pm = -INFINITY;
#pragma unroll
            for (int in = 0; in < 8; in++) {
                pm = fmaxf(pm, sacc[in][2 * rr]);
                pm = fmaxf(pm, sacc[in][2 * rr + 1]);
            }
            pm = fmaxf(pm, __shfl_xor_sync(0xffffffffu, pm, 1));
            pm = fmaxf(pm, __shfl_xor_sync(0xffffffffu, pm, 2));
            float mnew = fmaxf(m_i[rr], pm);
            float ps = 0.f;
#pragma unroll
            for (int in = 0; in < 8; in++) {
                float e0 = __expf(sacc[in][2 * rr]     - mnew);
                float e1 = __expf(sacc[in][2 * rr + 1] - mnew);
                sacc[in][2 * rr] = e0;
                sacc[in][2 * rr + 1] = e1;
                ps += e0 + e1;
            }
            ps += __shfl_xor_sync(0xffffffffu, ps, 1);
            ps += __shfl_xor_sync(0xffffffffu, ps, 2);
            alpha[rr] = __expf(m_i[rr] - mnew);
            l_i[rr] = l_i[rr] * alpha[rr] + ps;
            m_i[rr] = mnew;
        }
#pragma unroll
        for (int in = 0; in < 16; in++) {
            oacc[in][0] *= alpha[0]; oacc[in][1] *= alpha[0];
            oacc[in][2] *= alpha[1]; oacc[in][3] *= alpha[1];
        }

        // P -> shared, rounded once
        {
            int r0 = w * 16 + g;
#pragma unroll
            for (int in = 0; in < 8; in++) {
                int c = in * 8 + 2 * tg;
                *(float2*)(&Ps[r0 * PP + c]) = make_float2(
                    __uint_as_float(f2tf(sacc[in][0])),
                    __uint_as_float(f2tf(sacc[in][1])));
                *(float2*)(&Ps[(r0 + 8) * PP + c]) = make_float2(
                    __uint_as_float(f2tf(sacc[in][2])),
                    __uint_as_float(f2tf(sacc[in][3])));
            }
        }
        __syncwarp();

        // O += P @ V   (warp: 16 x 128, k = 64)
        {
            int r0 = w * 16 + g;
#pragma unroll
            for (int ik = 0; ik < 8; ik++) {
                uint32_t af[4];
                int c0 = ik * 8 + tg;
                af[0] = __float_as_uint(Ps[r0 * PP + c0]);
                af[1] = __float_as_uint(Ps[(r0 + 8) * PP + c0]);
                af[2] = __float_as_uint(Ps[r0 * PP + c0 + 4]);
                af[3] = __float_as_uint(Ps[(r0 + 8) * PP + c0 + 4]);
#pragma unroll
                for (int in = 0; in < 16; in++) {
                    uint32_t bf[2];
                    int krow = ik * 8 + tg;
                    int dcol = in * 8 + g;
                    bf[0] = __float_as_uint(Vsc[krow * DP + dcol]);
                    bf[1] = __float_as_uint(Vsc[(krow + 4) * DP + dcol]);
                    mma_tf32(oacc[in], af, bf);
                }
            }
        }
        __syncthreads();
    }

    // epilogue
    float inv0 = 1.f / l_i[0];
    float inv1 = 1.f / l_i[1];
    {
        int r = qt * ABR + w * 16 + g;
        float* Ob = Og + (size_t)bh * TSEQ * DHEAD;
#pragma unroll
        for (int in = 0; in < 16; in++) {
            int c = in * 8 + 2 * tg;
            *(float2*)(Ob + (size_t)r * DHEAD + c) =
                make_float2(oacc[in][0] * inv0, oacc[in][1] * inv0);
            *(float2*)(Ob + (size_t)(r + 8) * DHEAD + c) =
                make_float2(oacc[in][2] * inv1, oacc[in][3] * inv1);
        }
    }
}

// ---------------------------------------------------------------------------
// Host launcher
// ---------------------------------------------------------------------------
extern "C" void kernel_launch(void* const* d_in, const int* in_sizes, int n_in,
                              void* d_out, int out_size)
{
    const float* x     = (const float*)d_in[0];
    const float* Wqkv  = (const float*)d_in[1];
    const float* Wout  = (const float*)d_in[2];
    const float* Wgate = (const float*)d_in[3];
    const float* bgate = (const float*)d_in[4];
    float* out = (float*)d_out;

    float *qkv, *q, *k, *v, *o, *g, *xr, *wqkvr, *wgater, *woutr;
    float2* rtab;
    cudaGetSymbolAddress((void**)&qkv,    g_qkv);
    cudaGetSymbolAddress((void**)&q,      g_q);
    cudaGetSymbolAddress((void**)&k,      g_k);
    cudaGetSymbolAddress((void**)&v,      g_v);
    cudaGetSymbolAddress((void**)&o,      g_o);
    cudaGetSymbolAddress((void**)&g,      g_g);
    cudaGetSymbolAddress((void**)&xr,     g_xr);
    cudaGetSymbolAddress((void**)&wqkvr,  g_wqkvr);
    cudaGetSymbolAddress((void**)&wgater, g_wgater);
    cudaGetSymbolAddress((void**)&woutr,  g_woutr);
    cudaGetSymbolAddress((void**)&rtab,   g_rope);

    // 0) pre-round inputs to tf32 + RoPE table
    {
        int n4;
        n4 = (MROWS * DMOD) / 4;
        tf32_round_kernel<<<(n4 + 255) / 256, 256>>>(x, xr, n4);
        n4 = (DMOD * QKVN) / 4;
        tf32_round_kernel<<<(n4 + 255) / 256, 256>>>(Wqkv, wqkvr, n4);
        n4 = (DMOD * DMOD) / 4;
        tf32_round_kernel<<<(n4 + 255) / 256, 256>>>(Wgate, wgater, n4);
        tf32_round_kernel<<<(n4 + 255) / 256, 256>>>(Wout, woutr, n4);
        rope_table_kernel<<<(TSEQ * 64 + 255) / 256, 256>>>(rtab);
    }

    size_t gemm_smem = (size_t)(GST * BM * BKP + GST * BK * BNP) * sizeof(float);
    cudaFuncSetAttribute(mm_tf32_kernel,
                         cudaFuncAttributeMaxDynamicSharedMemorySize, (int)gemm_smem);

    // 1) QKV GEMM
    mm_tf32_kernel<<<dim3(QKVN / BN, MROWS / BM), 256, gemm_smem>>>(
        xr, wqkvr, qkv, MROWS, QKVN, DMOD, 0, nullptr, nullptr);

    // 2) RMSNorm + RoPE + permute (table-driven)
    norm_rope_kernel<<<BATCH * NHEAD * TSEQ, 128>>>(qkv, rtab, q, k, v);

    // 3) Flash attention
    size_t fl_smem = (size_t)FSM_FLOATS * sizeof(float);
    cudaFuncSetAttribute(flash_mma_kernel,
                         cudaFuncAttributeMaxDynamicSharedMemorySize, (int)fl_smem);
    flash_mma_kernel<<<dim3(TSEQ / ABR, BATCH * NHEAD), 256, fl_smem>>>(q, k, v, o);

    // 4) gate GEMM with fused sigmoid * attn epilogue
    mm_tf32_kernel<<<dim3(DMOD / BN, MROWS / BM), 256, gemm_smem>>>(
        xr, wgater, g, MROWS, DMOD, DMOD, 1, bgate, o);

    // 5) output GEMM
    mm_tf32_kernel<<<dim3(DMOD / BN, MROWS / BM), 256, gemm_smem>>>(
        g, woutr, out, MROWS, DMOD, DMOD, 0, nullptr, nullptr);
}

// round 6
// speedup vs baseline: 1.0286x; 1.0286x over previous
#include <cuda_runtime.h>
#include <math.h>
#include <stdint.h>

// Problem constants (fixed by setup_inputs)
#define BATCH 2
#define TSEQ  2048
#define DMOD  2048
#define NHEAD 16
#define DHEAD 128
#define MROWS (BATCH * TSEQ)        // 4096
#define QKVN  (3 * DMOD)            // 6144

// ---------------------------------------------------------------------------
// Scratch (static device globals; no runtime allocation)
// ---------------------------------------------------------------------------
__device__ float g_qkv[(size_t)MROWS * QKVN];
__device__ float g_q[(size_t)BATCH * NHEAD * TSEQ * DHEAD];
__device__ float g_k[(size_t)BATCH * NHEAD * TSEQ * DHEAD];
__device__ float g_v[(size_t)BATCH * NHEAD * TSEQ * DHEAD];
__device__ float g_o[(size_t)BATCH * NHEAD * TSEQ * DHEAD];
__device__ float g_g[(size_t)MROWS * DMOD];
// tf32-rounded copies of inputs
__device__ float g_xr[(size_t)MROWS * DMOD];
__device__ float g_wqkvr[(size_t)DMOD * QKVN];
__device__ float g_wgater[(size_t)DMOD * DMOD];
__device__ float g_woutr[(size_t)DMOD * DMOD];
// RoPE table: [t][j] -> (cos, sin), j = 0..63
__device__ float2 g_rope[(size_t)TSEQ * 64];

// ---------------------------------------------------------------------------
// Helpers
// ---------------------------------------------------------------------------
__device__ __forceinline__ uint32_t f2tf(float x) {
    uint32_t r;
    asm("cvt.rna.tf32.f32 %0, %1;" : "=r"(r) : "f"(x));
    return r;
}

__device__ __forceinline__ void mma_tf32(float* c, const uint32_t* a, const uint32_t* b) {
    asm volatile(
        "mma.sync.aligned.m16n8k8.row.col.f32.tf32.tf32.f32 "
        "{%0,%1,%2,%3},{%4,%5,%6,%7},{%8,%9},{%0,%1,%2,%3};\n"
        : "+f"(c[0]), "+f"(c[1]), "+f"(c[2]), "+f"(c[3])
        : "r"(a[0]), "r"(a[1]), "r"(a[2]), "r"(a[3]), "r"(b[0]), "r"(b[1]));
}

__device__ __forceinline__ void cpa16(void* dst, const void* src) {
    uint32_t d = (uint32_t)__cvta_generic_to_shared(dst);
    asm volatile("cp.async.cg.shared.global [%0], [%1], 16;" :: "r"(d), "l"(src));
}
#define CP_COMMIT() asm volatile("cp.async.commit_group;")
#define CP_WAIT0()  asm volatile("cp.async.wait_group 0;")
#define CP_WAIT1()  asm volatile("cp.async.wait_group 1;")
#define CP_WAIT2()  asm volatile("cp.async.wait_group 2;")

// ---------------------------------------------------------------------------
// RoPE table precompute (double precision, once): 2048 x 64 (cos, sin)
// ---------------------------------------------------------------------------
__global__ void __launch_bounds__(256)
rope_table_kernel(float2* __restrict__ tab)
{
    int idx = blockIdx.x * blockDim.x + threadIdx.x;
    if (idx < TSEQ * 64) {
        int t = idx >> 6;
        int j = idx & 63;
        double freq = exp(-((double)j / 64.0) * 9.210340371976184);  // ln(1e4)
        double ang = (double)t * freq;
        double sd, cd;
        sincos(ang, &sd, &cd);
        tab[idx] = make_float2((float)cd, (float)sd);
    }
}

// ---------------------------------------------------------------------------
// Elementwise tf32 rounding pass (float4 vectorized)
// ---------------------------------------------------------------------------
__global__ void __launch_bounds__(256)
tf32_round_kernel(const float* __restrict__ in, float* __restrict__ out, int n4)
{
    int i = blockIdx.x * blockDim.x + threadIdx.x;
    if (i < n4) {
        float4 v = ((const float4*)in)[i];
        v.x = __uint_as_float(f2tf(v.x));
        v.y = __uint_as_float(f2tf(v.y));
        v.z = __uint_as_float(f2tf(v.z));
        v.w = __uint_as_float(f2tf(v.w));
        ((float4*)out)[i] = v;
    }
}

// ---------------------------------------------------------------------------
// tf32 GEMM: C[M,N] = A[M,K] @ B[K,N] (A,B pre-rounded to tf32 values).
// BM=BN=128, BK=16, 3-stage cp.async ring, 256 threads, warp tile 32x64.
// mode 0: plain store; mode 1: C = round_tf32(sigmoid(acc+bias[n]) * gateO)
// ---------------------------------------------------------------------------
#define BM 128
#define BN 128
#define BK 16
#define BKP (BK + 4)    // 20
#define BNP (BN + 8)    // 136
#define GST 3           // stages

#define AS(s, r, c) Ash[(size_t)(s) * BM * BKP + (r) * BKP + (c)]
#define BS(s, r, c) Bsh[(size_t)(s) * BK * BNP + (r) * BNP + (c)]

__global__ void __launch_bounds__(256, 2)
mm_tf32_kernel(const float* __restrict__ A, const float* __restrict__ B,
               float* __restrict__ C, int M, int N, int K,
               int mode, const float* __restrict__ bias,
               const float* __restrict__ gateO)
{
    extern __shared__ float gsm[];
    float* Ash = gsm;
    float* Bsh = gsm + GST * BM * BKP;

    const int bx = blockIdx.x, by = blockIdx.y;
    const int tid = threadIdx.x;
    const int lane = tid & 31;
    const int warp = tid >> 5;
    const int wm = warp >> 1;
    const int wn = warp & 1;
    const int g  = lane >> 2;
    const int tg = lane & 3;

    const int aR0 = tid >> 2;
    const int aC  = (tid & 3) << 2;
    const int bR0 = tid >> 5;
    const int bC  = (tid & 31) << 2;

    const float* Abase = A + (size_t)(by * BM) * K;
    const float* Bbase = B + (size_t)(bx * BN);

    float acc[2][8][4];
#pragma unroll
    for (int im = 0; im < 2; im++)
#pragma unroll
        for (int in = 0; in < 8; in++)
#pragma unroll
            for (int j = 0; j < 4; j++) acc[im][in][j] = 0.f;

    const int KT = K / BK;

#pragma unroll
    for (int s = 0; s < 2; s++) {
        const int k0 = s * BK;
#pragma unroll
        for (int p = 0; p < 2; p++) {
            int r = aR0 + p * 64;
            cpa16(&AS(s, r, aC), Abase + (size_t)r * K + k0 + aC);
        }
#pragma unroll
        for (int p = 0; p < 2; p++) {
            int r = bR0 + p * 8;
            cpa16(&BS(s, r, bC), Bbase + (size_t)(k0 + r) * N + bC);
        }
        CP_COMMIT();
    }

    for (int kt = 0; kt < KT; kt++) {
        const int cur = kt % GST;
        if (kt + 1 < KT) { CP_WAIT1(); } else { CP_WAIT0(); }
        __syncthreads();

        if (kt + 2 < KT) {
            const int nxt = (kt + 2) % GST;
            const int k0 = (kt + 2) * BK;
#pragma unroll
            for (int p = 0; p < 2; p++) {
                int r = aR0 + p * 64;
                cpa16(&AS(nxt, r, aC), Abase + (size_t)r * K + k0 + aC);
            }
#pragma unroll
            for (int p = 0; p < 2; p++) {
                int r = bR0 + p * 8;
                cpa16(&BS(nxt, r, bC), Bbase + (size_t)(k0 + r) * N + bC);
            }
            CP_COMMIT();
        }

#pragma unroll
        for (int ik = 0; ik < 2; ik++) {
            uint32_t afr[2][4];
#pragma unroll
            for (int im = 0; im < 2; im++) {
                int r = wm * 32 + im * 16 + g;
                int c = ik * 8 + tg;
                afr[im][0] = __float_as_uint(AS(cur, r, c));
                afr[im][1] = __float_as_uint(AS(cur, r + 8, c));
                afr[im][2] = __float_as_uint(AS(cur, r, c + 4));
                afr[im][3] = __float_as_uint(AS(cur, r + 8, c + 4));
            }
            uint32_t bfr[8][2];
#pragma unroll
            for (int in = 0; in < 8; in++) {
                int cc = wn * 64 + in * 8 + g;
                int rk = ik * 8 + tg;
                bfr[in][0] = __float_as_uint(BS(cur, rk, cc));
                bfr[in][1] = __float_as_uint(BS(cur, rk + 4, cc));
            }
#pragma unroll
            for (int im = 0; im < 2; im++)
#pragma unroll
                for (int in = 0; in < 8; in++)
                    mma_tf32(acc[im][in], afr[im], bfr[in]);
        }
    }

    if (mode == 0) {
#pragma unroll
        for (int im = 0; im < 2; im++) {
            int r = by * BM + wm * 32 + im * 16 + g;
#pragma unroll
            for (int in = 0; in < 8; in++) {
                int c = bx * BN + wn * 64 + in * 8 + 2 * tg;
                *(float2*)(C + (size_t)r * N + c) =
                    make_float2(acc[im][in][0], acc[im][in][1]);
                *(float2*)(C + (size_t)(r + 8) * N + c) =
                    make_float2(acc[im][in][2], acc[im][in][3]);
            }
        }
    } else {
#pragma unroll
        for (int im = 0; im < 2; im++) {
            int rbase = by * BM + wm * 32 + im * 16 + g;
#pragma unroll
            for (int in = 0; in < 8; in++) {
                int cbase = bx * BN + wn * 64 + in * 8 + 2 * tg;
#pragma unroll
                for (int e = 0; e < 4; e++) {
                    int r = rbase + (e >> 1) * 8;
                    int c = cbase + (e & 1);
                    int b = r >> 11;
                    int t = r & (TSEQ - 1);
                    float z = acc[im][in][e] + bias[c];
                    float gte = 1.f / (1.f + expf(-z));
                    int h = c >> 7;
                    int dd = c & (DHEAD - 1);
                    size_t oidx = (((size_t)(b * NHEAD + h)) * TSEQ + t) * DHEAD + dd;
                    C[(size_t)r * N + c] = __uint_as_float(f2tf(gte * gateO[oidx]));
                }
            }
        }
    }
}

// ---------------------------------------------------------------------------
// RMSNorm + RoPE for q,k (plus v permute); outputs tf32-rounded.
// Q is pre-scaled by 1/sqrt(d). RoPE angles from precomputed table.
// ---------------------------------------------------------------------------
__global__ void __launch_bounds__(128)
norm_rope_kernel(const float* __restrict__ qkv,
                 const float2* __restrict__ rtab,
                 float* __restrict__ Qo, float* __restrict__ Ko,
                 float* __restrict__ Vo)
{
    const int rid = blockIdx.x;
    const int t  = rid & (TSEQ - 1);
    const int bh = rid >> 11;
    const int b  = bh >> 4;
    const int h  = bh & (NHEAD - 1);
    const int i  = threadIdx.x;

    const float* row = qkv + ((size_t)(b * TSEQ + t)) * QKVN + h * DHEAD;
    float qv = row[i];
    float kv = row[DMOD + i];
    float vv = row[2 * DMOD + i];

    float q2 = qv * qv, k2 = kv * kv;
#pragma unroll
    for (int o = 16; o; o >>= 1) {
        q2 += __shfl_xor_sync(0xffffffffu, q2, o);
        k2 += __shfl_xor_sync(0xffffffffu, k2, o);
    }
    __shared__ float rq[4], rk[4];
    if ((i & 31) == 0) { rq[i >> 5] = q2; rk[i >> 5] = k2; }
    __syncthreads();
    float ssq = rq[0] + rq[1] + rq[2] + rq[3];
    float ssk = rk[0] + rk[1] + rk[2] + rk[3];
    float rnq = rsqrtf(ssq * (1.f / DHEAD) + 1e-6f);
    float rnk = rsqrtf(ssk * (1.f / DHEAD) + 1e-6f);

    __shared__ float sq[DHEAD], sk[DHEAD];
    sq[i] = qv * rnq;
    sk[i] = kv * rnk;
    __syncthreads();

    const int j = i & 63;
    float2 cs = rtab[(size_t)t * 64 + j];
    float c = cs.x, s = cs.y;

    float oq, ok;
    if (i < 64) {
        oq = sq[i] * c - sq[i + 64] * s;
        ok = sk[i] * c - sk[i + 64] * s;
    } else {
        oq = sq[i - 64] * s + sq[i] * c;
        ok = sk[i - 64] * s + sk[i] * c;
    }
    const float qscale = 0.08838834764831845f;  // 1/sqrt(128), folded into Q
    size_t oidx = ((size_t)bh * TSEQ + t) * DHEAD + i;
    Qo[oidx] = __uint_as_float(f2tf(oq * qscale));
    Ko[oidx] = __uint_as_float(f2tf(ok));
    Vo[oidx] = __uint_as_float(f2tf(vv));
}

// ---------------------------------------------------------------------------
// Flash attention (causal), tf32 mma. Br=64, Bc=64, 128 threads (4 warps).
// Per-CTA smem 99KB -> 2 CTAs/SM. K double-buffered, V single-buffered with
// staged waits, Q overlaid on K buffer, P converted reg->reg via shfl
// (no P smem region). Scale pre-folded into Q.
// ---------------------------------------------------------------------------
#define ABR 64
#define ABC 64
#define DP  132   // d + 4

#define FK_OFF 0                       // [2][64][132] = 16896 floats
#define FV_OFF (2 * ABC * DP)          // [64][132]    =  8448 floats
#define FSM_FLOATS (FV_OFF + ABC * DP) // 25344 floats = 101376 B

__global__ void __launch_bounds__(128)
flash_mma_kernel(const float* __restrict__ Qg, const float* __restrict__ Kg,
                 const float* __restrict__ Vg, float* __restrict__ Og)
{
    extern __shared__ float fsm[];

    const int qt = (gridDim.x - 1) - blockIdx.x;   // heavy tiles first
    const int bh = blockIdx.y;
    const int tid  = threadIdx.x;
    const int lane = tid & 31;
    const int w    = tid >> 5;          // warp 0..3
    const int g    = lane >> 2;
    const int tg   = lane & 3;

    const float* Qb = Qg + (size_t)bh * TSEQ * DHEAD;
    const float* Kb = Kg + (size_t)bh * TSEQ * DHEAD;
    const float* Vb = Vg + (size_t)bh * TSEQ * DHEAD;

    const int ktmax = qt + 1;

    // --- prologue: stage Q (64x128) into K-buffer region, frags -> registers
#pragma unroll
    for (int p = 0; p < 16; p++) {
        int idx = tid + p * 128;
        int r = idx >> 5;
        int c = (idx & 31) << 2;
        cpa16(&fsm[r * DP + c], Qb + (size_t)(qt * ABR + r) * DHEAD + c);
    }
    CP_COMMIT();
    CP_WAIT0();
    __syncthreads();

    uint32_t qf[16][4];
    {
        int r = w * 16 + g;
#pragma unroll
        for (int ik = 0; ik < 16; ik++) {
            int c = ik * 8 + tg;
            qf[ik][0] = __float_as_uint(fsm[r * DP + c]);
            qf[ik][1] = __float_as_uint(fsm[(r + 8) * DP + c]);
            qf[ik][2] = __float_as_uint(fsm[r * DP + c + 4]);
            qf[ik][3] = __float_as_uint(fsm[(r + 8) * DP + c + 4]);
        }
    }
    __syncthreads();   // all warps done with Q before K(0) overwrites it

    // commit K(0) into K buffer 0
#pragma unroll
    for (int p = 0; p < 16; p++) {
        int idx = tid + p * 128;
        int r = idx >> 5;
        int c = (idx & 31) << 2;
        cpa16(&fsm[FK_OFF + r * DP + c], Kb + (size_t)r * DHEAD + c);
    }
    CP_COMMIT();

    float oacc[16][4];
#pragma unroll
    for (int in = 0; in < 16; in++)
#pragma unroll
        for (int j = 0; j < 4; j++) oacc[in][j] = 0.f;
    float m_i[2] = {-INFINITY, -INFINITY};
    float l_i[2] = {0.f, 0.f};

    const int rlo = qt * ABR + w * 16 + g;

    for (int kt = 0; kt < ktmax; kt++) {
        // commit V(kt) into the single V buffer (safe: end-of-iter sync)
        {
            float* vs = fsm + FV_OFF;
            const float* vp = Vb + (size_t)kt * ABC * DHEAD;
#pragma unroll
            for (int p = 0; p < 16; p++) {
                int idx = tid + p * 128;
                int r = idx >> 5;
                int c = (idx & 31) << 2;
                cpa16(&vs[r * DP + c], vp + (size_t)r * DHEAD + c);
            }
            CP_COMMIT();
        }
        // commit K(kt+1) into the other K buffer
        if (kt + 1 < ktmax) {
            float* ks = fsm + FK_OFF + ((kt + 1) & 1) * ABC * DP;
            const float* kp = Kb + (size_t)(kt + 1) * ABC * DHEAD;
#pragma unroll
            for (int p = 0; p < 16; p++) {
                int idx = tid + p * 128;
                int r = idx >> 5;
                int c = (idx & 31) << 2;
                cpa16(&ks[r * DP + c], kp + (size_t)r * DHEAD + c);
            }
            CP_COMMIT();
            CP_WAIT2();    // K(kt) done; V(kt), K(kt+1) may be in flight
        } else {
            CP_WAIT1();    // K(kt) done; V(kt) in flight
        }
        __syncthreads();

        const float* Ksc = fsm + FK_OFF + (kt & 1) * ABC * DP;

        // S = Q @ K^T  (warp: 16 x 64; 8 n-atoms)
        float sacc[8][4];
#pragma unroll
        for (int in = 0; in < 8; in++)
#pragma unroll
            for (int j = 0; j < 4; j++) sacc[in][j] = 0.f;

#pragma unroll
        for (int ik = 0; ik < 16; ik++) {
#pragma unroll
            for (int in = 0; in < 8; in++) {
                uint32_t bf[2];
                int srow = in * 8 + g;
                int dcol = ik * 8 + tg;
                bf[0] = __float_as_uint(Ksc[srow * DP + dcol]);
                bf[1] = __float_as_uint(Ksc[srow * DP + dcol + 4]);
                mma_tf32(sacc[in], qf[ik], bf);
            }
        }

        // causal mask (diagonal tile only)
        if (kt == qt) {
#pragma unroll
            for (int in = 0; in < 8; in++) {
                int cbase = kt * ABC + in * 8 + 2 * tg;
#pragma unroll
                for (int j = 0; j < 4; j++) {
                    int cg = cbase + (j & 1);
                    int rg = rlo + (j >> 1) * 8;
                    if (cg > rg) sacc[in][j] = -INFINITY;
                }
            }
        }

        // online softmax per owned row (rr=0: row g ; rr=1: row g+8)
        float alpha[2];
#pragma unroll
        for (int rr = 0; rr < 2; rr++) {
            float pm = -INFINITY;
#pragma unroll
            for (int in = 0; in < 8; in++) {
                pm = fmaxf(pm, sacc[in][2 * rr]);
                pm = fmaxf(pm, sacc[in][2 * rr + 1]);
            }
            pm = fmaxf(pm, __shfl_xor_sync(0xffffffffu, pm, 1));
            pm = fmaxf(pm, __shfl_xor_sync(0xffffffffu, pm, 2));
            float mnew = fmaxf(m_i[rr], pm);
            float ps = 0.f;
#pragma unroll
            for (int in = 0; in < 8; in++) {
                float e0 = __expf(sacc[in][2 * rr]     - mnew);
                float e1 = __expf(sacc[in][2 * rr + 1] - mnew);
                sacc[in][2 * rr] = e0;
                sacc[in][2 * rr + 1] = e1;
                ps += e0 + e1;
            }
            ps += __shfl_xor_sync(0xffffffffu, ps, 1);
            ps += __shfl_xor_sync(0xffffffffu, ps, 2);
            alpha[rr] = __expf(m_i[rr] - mnew);
            l_i[rr] = l_i[rr] * alpha[rr] + ps;
            m_i[rr] = mnew;
        }
#pragma unroll
        for (int in = 0; in < 16; in++) {
            oacc[in][0] *= alpha[0]; oacc[in][1] *= alpha[0];
            oacc[in][2] *= alpha[1]; oacc[in][3] *= alpha[1];
        }

        // wait for V(kt); K(kt+1) stays in flight
        if (kt + 1 < ktmax) { CP_WAIT1(); } else { CP_WAIT0(); }
        __syncthreads();

        const float* Vsc = fsm + FV_OFF;

        // O += P @ V  (P converted C-frag -> A-frag via shfl, no smem)
#pragma unroll
        for (int ik = 0; ik < 8; ik++) {
            const int srcA = (lane & 28) | (tg >> 1);
            const int srcB = srcA + 2;
            const bool odd = (tg & 1) != 0;
            float e0 = __shfl_sync(0xffffffffu, sacc[ik][0], srcA);
            float e1 = __shfl_sync(0xffffffffu, sacc[ik][1], srcA);
            float e2 = __shfl_sync(0xffffffffu, sacc[ik][2], srcA);
            float e3 = __shfl_sync(0xffffffffu, sacc[ik][3], srcA);
            float f0 = __shfl_sync(0xffffffffu, sacc[ik][0], srcB);
            float f1 = __shfl_sync(0xffffffffu, sacc[ik][1], srcB);
            float f2 = __shfl_sync(0xffffffffu, sacc[ik][2], srcB);
            float f3 = __shfl_sync(0xffffffffu, sacc[ik][3], srcB);
            uint32_t af[4];
            af[0] = f2tf(odd ? e1 : e0);   // P[g][tg]
            af[1] = f2tf(odd ? e3 : e2);   // P[g+8][tg]
            af[2] = f2tf(odd ? f1 : f0);   // P[g][tg+4]
            af[3] = f2tf(odd ? f3 : f2);   // P[g+8][tg+4]
#pragma unroll
            for (int in = 0; in < 16; in++) {
                uint32_t bf[2];
                int krow = ik * 8 + tg;
                int dcol = in * 8 + g;
                bf[0] = __float_as_uint(Vsc[krow * DP + dcol]);
                bf[1] = __float_as_uint(Vsc[(krow + 4) * DP + dcol]);
                mma_tf32(oacc[in], af, bf);
            }
        }
        __syncthreads();   // protect V (single buffer) + K buffers for refill
    }

    // epilogue
    float inv0 = 1.f / l_i[0];
    float inv1 = 1.f / l_i[1];
    {
        int r = qt * ABR + w * 16 + g;
        float* Ob = Og + (size_t)bh * TSEQ * DHEAD;
#pragma unroll
        for (int in = 0; in < 16; in++) {
            int c = in * 8 + 2 * tg;
            *(float2*)(Ob + (size_t)r * DHEAD + c) =
                make_float2(oacc[in][0] * inv0, oacc[in][1] * inv0);
            *(float2*)(Ob + (size_t)(r + 8) * DHEAD + c) =
                make_float2(oacc[in][2] * inv1, oacc[in][3] * inv1);
        }
    }
}

// ---------------------------------------------------------------------------
// Host launcher
// ---------------------------------------------------------------------------
extern "C" void kernel_launch(void* const* d_in, const int* in_sizes, int n_in,
                              void* d_out, int out_size)
{
    const float* x     = (const float*)d_in[0];
    const float* Wqkv  = (const float*)d_in[1];
    const float* Wout  = (const float*)d_in[2];
    const float* Wgate = (const float*)d_in[3];
    const float* bgate = (const float*)d_in[4];
    float* out = (float*)d_out;

    float *qkv, *q, *k, *v, *o, *g, *xr, *wqkvr, *wgater, *woutr;
    float2* rtab;
    cudaGetSymbolAddress((void**)&qkv,    g_qkv);
    cudaGetSymbolAddress((void**)&q,      g_q);
    cudaGetSymbolAddress((void**)&k,      g_k);
    cudaGetSymbolAddress((void**)&v,      g_v);
    cudaGetSymbolAddress((void**)&o,      g_o);
    cudaGetSymbolAddress((void**)&g,      g_g);
    cudaGetSymbolAddress((void**)&xr,     g_xr);
    cudaGetSymbolAddress((void**)&wqkvr,  g_wqkvr);
    cudaGetSymbolAddress((void**)&wgater, g_wgater);
    cudaGetSymbolAddress((void**)&woutr,  g_woutr);
    cudaGetSymbolAddress((void**)&rtab,   g_rope);

    // 0) pre-round inputs to tf32 + RoPE table
    {
        int n4;
        n4 = (MROWS * DMOD) / 4;
        tf32_round_kernel<<<(n4 + 255) / 256, 256>>>(x, xr, n4);
        n4 = (DMOD * QKVN) / 4;
        tf32_round_kernel<<<(n4 + 255) / 256, 256>>>(Wqkv, wqkvr, n4);
        n4 = (DMOD * DMOD) / 4;
        tf32_round_kernel<<<(n4 + 255) / 256, 256>>>(Wgate, wgater, n4);
        tf32_round_kernel<<<(n4 + 255) / 256, 256>>>(Wout, woutr, n4);
        rope_table_kernel<<<(TSEQ * 64 + 255) / 256, 256>>>(rtab);
    }

    size_t gemm_smem = (size_t)(GST * BM * BKP + GST * BK * BNP) * sizeof(float);
    cudaFuncSetAttribute(mm_tf32_kernel,
                         cudaFuncAttributeMaxDynamicSharedMemorySize, (int)gemm_smem);

    // 1) QKV GEMM
    mm_tf32_kernel<<<dim3(QKVN / BN, MROWS / BM), 256, gemm_smem>>>(
        xr, wqkvr, qkv, MROWS, QKVN, DMOD, 0, nullptr, nullptr);

    // 2) RMSNorm + RoPE + permute (table-driven)
    norm_rope_kernel<<<BATCH * NHEAD * TSEQ, 128>>>(qkv, rtab, q, k, v);

    // 3) Flash attention (Br=64, 2 CTAs/SM)
    size_t fl_smem = (size_t)FSM_FLOATS * sizeof(float);
    cudaFuncSetAttribute(flash_mma_kernel,
                         cudaFuncAttributeMaxDynamicSharedMemorySize, (int)fl_smem);
    flash_mma_kernel<<<dim3(TSEQ / ABR, BATCH * NHEAD), 128, fl_smem>>>(q, k, v, o);

    // 4) gate GEMM with fused sigmoid * attn epilogue
    mm_tf32_kernel<<<dim3(DMOD / BN, MROWS / BM), 256, gemm_smem>>>(
        xr, wgater, g, MROWS, DMOD, DMOD, 1, bgate, o);

    // 5) output GEMM
    mm_tf32_kernel<<<dim3(DMOD / BN, MROWS / BM), 256, gemm_smem>>>(
        g, woutr, out, MROWS, DMOD, DMOD, 0, nullptr, nullptr);
}

// round 7
// speedup vs baseline: 1.0810x; 1.0509x over previous
#include <cuda_runtime.h>
#include <math.h>
#include <stdint.h>

// Problem constants (fixed by setup_inputs)
#define BATCH 2
#define TSEQ  2048
#define DMOD  2048
#define NHEAD 16
#define DHEAD 128
#define MROWS (BATCH * TSEQ)        // 4096
#define QKVN  (3 * DMOD)            // 6144

// ---------------------------------------------------------------------------
// Scratch (static device globals; no runtime allocation)
// ---------------------------------------------------------------------------
__device__ float g_qkv[(size_t)MROWS * QKVN];
__device__ float g_q[(size_t)BATCH * NHEAD * TSEQ * DHEAD];
__device__ float g_k[(size_t)BATCH * NHEAD * TSEQ * DHEAD];
__device__ float g_v[(size_t)BATCH * NHEAD * TSEQ * DHEAD];
__device__ float g_o[(size_t)BATCH * NHEAD * TSEQ * DHEAD];
__device__ float g_g[(size_t)MROWS * DMOD];
// tf32-rounded copies of inputs
__device__ float g_xr[(size_t)MROWS * DMOD];
__device__ float g_wqkvr[(size_t)DMOD * QKVN];
__device__ float g_wgater[(size_t)DMOD * DMOD];
__device__ float g_woutr[(size_t)DMOD * DMOD];
// RoPE table: [t][j] -> (cos, sin), j = 0..63
__device__ float2 g_rope[(size_t)TSEQ * 64];

// ---------------------------------------------------------------------------
// Helpers
// ---------------------------------------------------------------------------
__device__ __forceinline__ uint32_t f2tf(float x) {
    uint32_t r;
    asm("cvt.rna.tf32.f32 %0, %1;" : "=r"(r) : "f"(x));
    return r;
}

__device__ __forceinline__ void mma_tf32(float* c, const uint32_t* a, const uint32_t* b) {
    asm volatile(
        "mma.sync.aligned.m16n8k8.row.col.f32.tf32.tf32.f32 "
        "{%0,%1,%2,%3},{%4,%5,%6,%7},{%8,%9},{%0,%1,%2,%3};\n"
        : "+f"(c[0]), "+f"(c[1]), "+f"(c[2]), "+f"(c[3])
        : "r"(a[0]), "r"(a[1]), "r"(a[2]), "r"(a[3]), "r"(b[0]), "r"(b[1]));
}

__device__ __forceinline__ void cpa16(void* dst, const void* src) {
    uint32_t d = (uint32_t)__cvta_generic_to_shared(dst);
    asm volatile("cp.async.cg.shared.global [%0], [%1], 16;" :: "r"(d), "l"(src));
}
#define CP_COMMIT() asm volatile("cp.async.commit_group;")
#define CP_WAIT0()  asm volatile("cp.async.wait_group 0;")
#define CP_WAIT1()  asm volatile("cp.async.wait_group 1;")
#define CP_WAIT2()  asm volatile("cp.async.wait_group 2;")

// ---------------------------------------------------------------------------
// RoPE table precompute (double precision, once): 2048 x 64 (cos, sin)
// ---------------------------------------------------------------------------
__global__ void __launch_bounds__(256)
rope_table_kernel(float2* __restrict__ tab)
{
    int idx = blockIdx.x * blockDim.x + threadIdx.x;
    if (idx < TSEQ * 64) {
        int t = idx >> 6;
        int j = idx & 63;
        double freq = exp(-((double)j / 64.0) * 9.210340371976184);  // ln(1e4)
        double ang = (double)t * freq;
        double sd, cd;
        sincos(ang, &sd, &cd);
        tab[idx] = make_float2((float)cd, (float)sd);
    }
}

// ---------------------------------------------------------------------------
// Fused tf32 rounding pass for all 4 input arrays (one launch)
// ---------------------------------------------------------------------------
#define RN1 ((MROWS * DMOD) / 4)            // x      : 2097152 float4
#define RN2 ((DMOD * QKVN) / 4)             // W_qkv  : 3145728
#define RN3 ((DMOD * DMOD) / 4)             // W_gate : 1048576
#define RNTOT (RN1 + RN2 + 2 * RN3)         // 7340032

__global__ void __launch_bounds__(256)
fused_round_kernel(const float* __restrict__ x,  float* __restrict__ xr,
                   const float* __restrict__ w1, float* __restrict__ w1r,
                   const float* __restrict__ w2, float* __restrict__ w2r,
                   const float* __restrict__ w3, float* __restrict__ w3r)
{
    int i = blockIdx.x * blockDim.x + threadIdx.x;
    if (i >= RNTOT) return;
    const float4* src;
    float4* dst;
    int off;
    if (i < RN1)                   { src = (const float4*)x;  dst = (float4*)xr;  off = i; }
    else if (i < RN1 + RN2)        { src = (const float4*)w1; dst = (float4*)w1r; off = i - RN1; }
    else if (i < RN1 + RN2 + RN3)  { src = (const float4*)w2; dst = (float4*)w2r; off = i - RN1 - RN2; }
    else                           { src = (const float4*)w3; dst = (float4*)w3r; off = i - RN1 - RN2 - RN3; }
    float4 v = src[off];
    v.x = __uint_as_float(f2tf(v.x));
    v.y = __uint_as_float(f2tf(v.y));
    v.z = __uint_as_float(f2tf(v.z));
    v.w = __uint_as_float(f2tf(v.w));
    dst[off] = v;
}

// ---------------------------------------------------------------------------
// tf32 GEMM: C[M,N] = A[M,K] @ B[K,N] (A,B pre-rounded to tf32 values).
// BM=BN=128, BK=16, 3-stage cp.async ring, 256 threads, warp tile 32x64.
// mode 0: plain store; mode 1: C = round_tf32(sigmoid(acc+bias[n]) * gateO)
// ---------------------------------------------------------------------------
#define BM 128
#define BN 128
#define BK 16
#define BKP (BK + 4)    // 20
#define BNP (BN + 8)    // 136
#define GST 3           // stages

#define AS(s, r, c) Ash[(size_t)(s) * BM * BKP + (r) * BKP + (c)]
#define BS(s, r, c) Bsh[(size_t)(s) * BK * BNP + (r) * BNP + (c)]

__global__ void __launch_bounds__(256, 2)
mm_tf32_kernel(const float* __restrict__ A, const float* __restrict__ B,
               float* __restrict__ C, int M, int N, int K,
               int mode, const float* __restrict__ bias,
               const float* __restrict__ gateO)
{
    extern __shared__ float gsm[];
    float* Ash = gsm;
    float* Bsh = gsm + GST * BM * BKP;

    const int bx = blockIdx.x, by = blockIdx.y;
    const int tid = threadIdx.x;
    const int lane = tid & 31;
    const int warp = tid >> 5;
    const int wm = warp >> 1;
    const int wn = warp & 1;
    const int g  = lane >> 2;
    const int tg = lane & 3;

    const int aR0 = tid >> 2;
    const int aC  = (tid & 3) << 2;
    const int bR0 = tid >> 5;
    const int bC  = (tid & 31) << 2;

    const float* Abase = A + (size_t)(by * BM) * K;
    const float* Bbase = B + (size_t)(bx * BN);

    float acc[2][8][4];
#pragma unroll
    for (int im = 0; im < 2; im++)
#pragma unroll
        for (int in = 0; in < 8; in++)
#pragma unroll
            for (int j = 0; j < 4; j++) acc[im][in][j] = 0.f;

    const int KT = K / BK;

#pragma unroll
    for (int s = 0; s < 2; s++) {
        const int k0 = s * BK;
#pragma unroll
        for (int p = 0; p < 2; p++) {
            int r = aR0 + p * 64;
            cpa16(&AS(s, r, aC), Abase + (size_t)r * K + k0 + aC);
        }
#pragma unroll
        for (int p = 0; p < 2; p++) {
            int r = bR0 + p * 8;
            cpa16(&BS(s, r, bC), Bbase + (size_t)(k0 + r) * N + bC);
        }
        CP_COMMIT();
    }

    for (int kt = 0; kt < KT; kt++) {
        const int cur = kt % GST;
        if (kt + 1 < KT) { CP_WAIT1(); } else { CP_WAIT0(); }
        __syncthreads();

        if (kt + 2 < KT) {
            const int nxt = (kt + 2) % GST;
            const int k0 = (kt + 2) * BK;
#pragma unroll
            for (int p = 0; p < 2; p++) {
                int r = aR0 + p * 64;
                cpa16(&AS(nxt, r, aC), Abase + (size_t)r * K + k0 + aC);
            }
#pragma unroll
            for (int p = 0; p < 2; p++) {
                int r = bR0 + p * 8;
                cpa16(&BS(nxt, r, bC), Bbase + (size_t)(k0 + r) * N + bC);
            }
            CP_COMMIT();
        }

#pragma unroll
        for (int ik = 0; ik < 2; ik++) {
            uint32_t afr[2][4];
#pragma unroll
            for (int im = 0; im < 2; im++) {
                int r = wm * 32 + im * 16 + g;
                int c = ik * 8 + tg;
                afr[im][0] = __float_as_uint(AS(cur, r, c));
                afr[im][1] = __float_as_uint(AS(cur, r + 8, c));
                afr[im][2] = __float_as_uint(AS(cur, r, c + 4));
                afr[im][3] = __float_as_uint(AS(cur, r + 8, c + 4));
            }
            uint32_t bfr[8][2];
#pragma unroll
            for (int in = 0; in < 8; in++) {
                int cc = wn * 64 + in * 8 + g;
                int rk = ik * 8 + tg;
                bfr[in][0] = __float_as_uint(BS(cur, rk, cc));
                bfr[in][1] = __float_as_uint(BS(cur, rk + 4, cc));
            }
#pragma unroll
            for (int im = 0; im < 2; im++)
#pragma unroll
                for (int in = 0; in < 8; in++)
                    mma_tf32(acc[im][in], afr[im], bfr[in]);
        }
    }

    if (mode == 0) {
#pragma unroll
        for (int im = 0; im < 2; im++) {
            int r = by * BM + wm * 32 + im * 16 + g;
#pragma unroll
            for (int in = 0; in < 8; in++) {
                int c = bx * BN + wn * 64 + in * 8 + 2 * tg;
                *(float2*)(C + (size_t)r * N + c) =
                    make_float2(acc[im][in][0], acc[im][in][1]);
                *(float2*)(C + (size_t)(r + 8) * N + c) =
                    make_float2(acc[im][in][2], acc[im][in][3]);
            }
        }
    } else {
#pragma unroll
        for (int im = 0; im < 2; im++) {
            int rbase = by * BM + wm * 32 + im * 16 + g;
#pragma unroll
            for (int in = 0; in < 8; in++) {
                int cbase = bx * BN + wn * 64 + in * 8 + 2 * tg;
#pragma unroll
                for (int e = 0; e < 4; e++) {
                    int r = rbase + (e >> 1) * 8;
                    int c = cbase + (e & 1);
                    int b = r >> 11;
                    int t = r & (TSEQ - 1);
                    float z = acc[im][in][e] + bias[c];
                    float gte = 1.f / (1.f + expf(-z));
                    int h = c >> 7;
                    int dd = c & (DHEAD - 1);
                    size_t oidx = (((size_t)(b * NHEAD + h)) * TSEQ + t) * DHEAD + dd;
                    C[(size_t)r * N + c] = __uint_as_float(f2tf(gte * gateO[oidx]));
                }
            }
        }
    }
}

// ---------------------------------------------------------------------------
// RMSNorm + RoPE for q,k (plus v permute); outputs tf32-rounded.
// Q is pre-scaled by 1/sqrt(d). RoPE angles from precomputed table.
// ---------------------------------------------------------------------------
__global__ void __launch_bounds__(128)
norm_rope_kernel(const float* __restrict__ qkv,
                 const float2* __restrict__ rtab,
                 float* __restrict__ Qo, float* __restrict__ Ko,
                 float* __restrict__ Vo)
{
    const int rid = blockIdx.x;
    const int t  = rid & (TSEQ - 1);
    const int bh = rid >> 11;
    const int b  = bh >> 4;
    const int h  = bh & (NHEAD - 1);
    const int i  = threadIdx.x;

    const float* row = qkv + ((size_t)(b * TSEQ + t)) * QKVN + h * DHEAD;
    float qv = row[i];
    float kv = row[DMOD + i];
    float vv = row[2 * DMOD + i];

    float q2 = qv * qv, k2 = kv * kv;
#pragma unroll
    for (int o = 16; o; o >>= 1) {
        q2 += __shfl_xor_sync(0xffffffffu, q2, o);
        k2 += __shfl_xor_sync(0xffffffffu, k2, o);
    }
    __shared__ float rq[4], rk[4];
    if ((i & 31) == 0) { rq[i >> 5] = q2; rk[i >> 5] = k2; }
    __syncthreads();
    float ssq = rq[0] + rq[1] + rq[2] + rq[3];
    float ssk = rk[0] + rk[1] + rk[2] + rk[3];
    float rnq = rsqrtf(ssq * (1.f / DHEAD) + 1e-6f);
    float rnk = rsqrtf(ssk * (1.f / DHEAD) + 1e-6f);

    __shared__ float sq[DHEAD], sk[DHEAD];
    sq[i] = qv * rnq;
    sk[i] = kv * rnk;
    __syncthreads();

    const int j = i & 63;
    float2 cs = rtab[(size_t)t * 64 + j];
    float c = cs.x, s = cs.y;

    float oq, ok;
    if (i < 64) {
        oq = sq[i] * c - sq[i + 64] * s;
        ok = sk[i] * c - sk[i + 64] * s;
    } else {
        oq = sq[i - 64] * s + sq[i] * c;
        ok = sk[i - 64] * s + sk[i] * c;
    }
    const float qscale = 0.08838834764831845f;  // 1/sqrt(128), folded into Q
    size_t oidx = ((size_t)bh * TSEQ + t) * DHEAD + i;
    Qo[oidx] = __uint_as_float(f2tf(oq * qscale));
    Ko[oidx] = __uint_as_float(f2tf(ok));
    Vo[oidx] = __uint_as_float(f2tf(vv));
}

// ---------------------------------------------------------------------------
// Flash attention (causal), tf32 mma. Br=128, Bc=64, 256 threads (8 warps).
// K and V triple-buffered with a 2-tile prefetch window (DRAM latency cover).
// Q staging overlays K buffers 0-1; P converted reg->reg via shfl (no P smem).
// Scale pre-folded into Q. Smem = 198 KB, 1 CTA/SM.
// ---------------------------------------------------------------------------
#define ABR 128
#define ABC 64
#define DP  132            // d + 4
#define KTF (ABR / ABC)    // 2 kv-tiles per q-tile
#define NBUF 3
#define TILEF (ABC * DP)   // 8448 floats per tile buffer
#define FSM_FLOATS (2 * NBUF * TILEF)   // 50688 floats = 202752 B

__global__ void __launch_bounds__(256, 1)
flash_mma_kernel(const float* __restrict__ Qg, const float* __restrict__ Kg,
                 const float* __restrict__ Vg, float* __restrict__ Og)
{
    extern __shared__ float fsm[];

    const int qt = (gridDim.x - 1) - blockIdx.x;   // heavy tiles first
    const int bh = blockIdx.y;
    const int tid  = threadIdx.x;
    const int lane = tid & 31;
    const int w    = tid >> 5;          // warp 0..7
    const int g    = lane >> 2;
    const int tg   = lane & 3;

    const float* Qb = Qg + (size_t)bh * TSEQ * DHEAD;
    const float* Kb = Kg + (size_t)bh * TSEQ * DHEAD;
    const float* Vb = Vg + (size_t)bh * TSEQ * DHEAD;

    const int ktmax = KTF * (qt + 1);

    // --- prologue: stage Q (128x128) into K buffers 0-1 region
#pragma unroll
    for (int p = 0; p < 16; p++) {
        int idx = tid + p * 256;
        int r = idx >> 5;
        int c = (idx & 31) << 2;
        cpa16(&fsm[r * DP + c], Qb + (size_t)(qt * ABR + r) * DHEAD + c);
    }
    CP_COMMIT();
    CP_WAIT0();
    __syncthreads();

    uint32_t qf[16][4];
    {
        int r = w * 16 + g;
#pragma unroll
        for (int ik = 0; ik < 16; ik++) {
            int c = ik * 8 + tg;
            qf[ik][0] = __float_as_uint(fsm[r * DP + c]);
            qf[ik][1] = __float_as_uint(fsm[(r + 8) * DP + c]);
            qf[ik][2] = __float_as_uint(fsm[r * DP + c + 4]);
            qf[ik][3] = __float_as_uint(fsm[(r + 8) * DP + c + 4]);
        }
    }
    __syncthreads();   // all warps done with Q before K(0)/K(1) overwrite it

    // prefetch tiles 0 and 1 (one group each: {K,V})
#pragma unroll
    for (int s = 0; s < 2; s++) {
        if (s < ktmax) {
            float* ks = fsm + s * TILEF;
            float* vs = fsm + (NBUF + s) * TILEF;
            const float* kp = Kb + (size_t)s * ABC * DHEAD;
            const float* vp = Vb + (size_t)s * ABC * DHEAD;
#pragma unroll
            for (int p = 0; p < 8; p++) {
                int idx = tid + p * 256;
                int r = idx >> 5;
                int c = (idx & 31) << 2;
                cpa16(&ks[r * DP + c], kp + (size_t)r * DHEAD + c);
                cpa16(&vs[r * DP + c], vp + (size_t)r * DHEAD + c);
            }
            CP_COMMIT();
        }
    }

    float oacc[16][4];
#pragma unroll
    for (int in = 0; in < 16; in++)
#pragma unroll
        for (int j = 0; j < 4; j++) oacc[in][j] = 0.f;
    float m_i[2] = {-INFINITY, -INFINITY};
    float l_i[2] = {0.f, 0.f};

    const int rlo = qt * ABR + w * 16 + g;

    for (int kt = 0; kt < ktmax; kt++) {
        // prefetch tile kt+2 into buffer (kt+2)%3 (freed by prev-iter sync)
        if (kt + 2 < ktmax) {
            int s = (kt + 2) % NBUF;
            float* ks = fsm + s * TILEF;
            float* vs = fsm + (NBUF + s) * TILEF;
            const float* kp = Kb + (size_t)(kt + 2) * ABC * DHEAD;
            const float* vp = Vb + (size_t)(kt + 2) * ABC * DHEAD;
#pragma unroll
            for (int p = 0; p < 8; p++) {
                int idx = tid + p * 256;
                int r = idx >> 5;
                int c = (idx & 31) << 2;
                cpa16(&ks[r * DP + c], kp + (size_t)r * DHEAD + c);
                cpa16(&vs[r * DP + c], vp + (size_t)r * DHEAD + c);
            }
            CP_COMMIT();
            CP_WAIT2();    // tile kt complete; kt+1, kt+2 in flight
        } else if (kt + 1 < ktmax) {
            CP_WAIT1();    // tile kt complete; kt+1 in flight
        } else {
            CP_WAIT0();
        }
        __syncthreads();

        const float* Ksc = fsm + (kt % NBUF) * TILEF;
        const float* Vsc = fsm + (NBUF + kt % NBUF) * TILEF;

        // S = Q @ K^T  (warp: 16 x 64; 8 n-atoms)
        float sacc[8][4];
#pragma unroll
        for (int in = 0; in < 8; in++)
#pragma unroll
            for (int j = 0; j < 4; j++) sacc[in][j] = 0.f;

#pragma unroll
        for (int ik = 0; ik < 16; ik++) {
#pragma unroll
            for (int in = 0; in < 8; in++) {
                uint32_t bf[2];
                int srow = in * 8 + g;
                int dcol = ik * 8 + tg;
                bf[0] = __float_as_uint(Ksc[srow * DP + dcol]);
                bf[1] = __float_as_uint(Ksc[srow * DP + dcol + 4]);
                mma_tf32(sacc[in], qf[ik], bf);
            }
        }

        // causal mask (band tiles only)
        if (kt >= KTF * qt) {
#pragma unroll
            for (int in = 0; in < 8; in++) {
                int cbase = kt * ABC + in * 8 + 2 * tg;
#pragma unroll
                for (int j = 0; j < 4; j++) {
                    int cg = cbase + (j & 1);
                    int rg = rlo + (j >> 1) * 8;
                    if (cg > rg) sacc[in][j] = -INFINITY;
                }
            }
        }

        // online softmax per owned row (rr=0: row g ; rr=1: row g+8)
        float alpha[2];
#pragma unroll
        for (int rr = 0; rr < 2; rr++) {
            float pm = -INFINITY;
#pragma unroll
            for (int in = 0; in < 8; in++) {
                pm = fmaxf(pm, sacc[in][2 * rr]);
                pm = fmaxf(pm, sacc[in][2 * rr + 1]);
            }
            pm = fmaxf(pm, __shfl_xor_sync(0xffffffffu, pm, 1));
            pm = fmaxf(pm, __shfl_xor_sync(0xffffffffu, pm, 2));
            float mnew = fmaxf(m_i[rr], pm);
            float ps = 0.f;
#pragma unroll
            for (int in = 0; in < 8; in++) {
                float e0 = __expf(sacc[in][2 * rr]     - mnew);
                float e1 = __expf(sacc[in][2 * rr + 1] - mnew);
                sacc[in][2 * rr] = e0;
                sacc[in][2 * rr + 1] = e1;
                ps += e0 + e1;
            }
            ps += __shfl_xor_sync(0xffffffffu, ps, 1);
            ps += __shfl_xor_sync(0xffffffffu, ps, 2);
            alpha[rr] = __expf(m_i[rr] - mnew);
            l_i[rr] = l_i[rr] * alpha[rr] + ps;
            m_i[rr] = mnew;
        }
#pragma unroll
        for (int in = 0; in < 16; in++) {
            oacc[in][0] *= alpha[0]; oacc[in][1] *= alpha[0];
            oacc[in][2] *= alpha[1]; oacc[in][3] *= alpha[1];
        }

        // O += P @ V  (P converted C-frag -> A-frag via shfl, no smem)
#pragma unroll
        for (int ik = 0; ik < 8; ik++) {
            const int srcA = (lane & 28) | (tg >> 1);
            const int srcB = srcA + 2;
            const bool odd = (tg & 1) != 0;
            float e0 = __shfl_sync(0xffffffffu, sacc[ik][0], srcA);
            float e1 = __shfl_sync(0xffffffffu, sacc[ik][1], srcA);
            float e2 = __shfl_sync(0xffffffffu, sacc[ik][2], srcA);
            float e3 = __shfl_sync(0xffffffffu, sacc[ik][3], srcA);
            float f0 = __shfl_sync(0xffffffffu, sacc[ik][0], srcB);
            float f1 = __shfl_sync(0xffffffffu, sacc[ik][1], srcB);
            float f2 = __shfl_sync(0xffffffffu, sacc[ik][2], srcB);
            float f3 = __shfl_sync(0xffffffffu, sacc[ik][3], srcB);
            uint32_t af[4];
            af[0] = f2tf(odd ? e1 : e0);   // P[g][tg]
            af[1] = f2tf(odd ? e3 : e2);   // P[g+8][tg]
            af[2] = f2tf(odd ? f1 : f0);   // P[g][tg+4]
            af[3] = f2tf(odd ? f3 : f2);   // P[g+8][tg+4]
#pragma unroll
            for (int in = 0; in < 16; in++) {
                uint32_t bf[2];
                int krow = ik * 8 + tg;
                int dcol = in * 8 + g;
                bf[0] = __float_as_uint(Vsc[krow * DP + dcol]);
                bf[1] = __float_as_uint(Vsc[(krow + 4) * DP + dcol]);
                mma_tf32(oacc[in], af, bf);
            }
        }
        __syncthreads();   // all warps done with buffer kt%3 before refill
    }

    // epilogue
    float inv0 = 1.f / l_i[0];
    float inv1 = 1.f / l_i[1];
    {
        int r = qt * ABR + w * 16 + g;
        float* Ob = Og + (size_t)bh * TSEQ * DHEAD;
#pragma unroll
        for (int in = 0; in < 16; in++) {
            int c = in * 8 + 2 * tg;
            *(float2*)(Ob + (size_t)r * DHEAD + c) =
                make_float2(oacc[in][0] * inv0, oacc[in][1] * inv0);
            *(float2*)(Ob + (size_t)(r + 8) * DHEAD + c) =
                make_float2(oacc[in][2] * inv1, oacc[in][3] * inv1);
        }
    }
}

// ---------------------------------------------------------------------------
// Host launcher
// ---------------------------------------------------------------------------
extern "C" void kernel_launch(void* const* d_in, const int* in_sizes, int n_in,
                              void* d_out, int out_size)
{
    const float* x     = (const float*)d_in[0];
    const float* Wqkv  = (const float*)d_in[1];
    const float* Wout  = (const float*)d_in[2];
    const float* Wgate = (const float*)d_in[3];
    const float* bgate = (const float*)d_in[4];
    float* out = (float*)d_out;

    float *qkv, *q, *k, *v, *o, *g, *xr, *wqkvr, *wgater, *woutr;
    float2* rtab;
    cudaGetSymbolAddress((void**)&qkv,    g_qkv);
    cudaGetSymbolAddress((void**)&q,      g_q);
    cudaGetSymbolAddress((void**)&k,      g_k);
    cudaGetSymbolAddress((void**)&v,      g_v);
    cudaGetSymbolAddress((void**)&o,      g_o);
    cudaGetSymbolAddress((void**)&g,      g_g);
    cudaGetSymbolAddress((void**)&xr,     g_xr);
    cudaGetSymbolAddress((void**)&wqkvr,  g_wqkvr);
    cudaGetSymbolAddress((void**)&wgater, g_wgater);
    cudaGetSymbolAddress((void**)&woutr,  g_woutr);
    cudaGetSymbolAddress((void**)&rtab,   g_rope);

    // 0) fused tf32 pre-round (1 launch) + RoPE table (1 launch)
    fused_round_kernel<<<(RNTOT + 255) / 256, 256>>>(
        x, xr, Wqkv, wqkvr, Wgate, wgater, Wout, woutr);
    rope_table_kernel<<<(TSEQ * 64 + 255) / 256, 256>>>(rtab);

    size_t gemm_smem = (size_t)(GST * BM * BKP + GST * BK * BNP) * sizeof(float);
    cudaFuncSetAttribute(mm_tf32_kernel,
                         cudaFuncAttributeMaxDynamicSharedMemorySize, (int)gemm_smem);

    // 1) QKV GEMM
    mm_tf32_kernel<<<dim3(QKVN / BN, MROWS / BM), 256, gemm_smem>>>(
        xr, wqkvr, qkv, MROWS, QKVN, DMOD, 0, nullptr, nullptr);

    // 2) RMSNorm + RoPE + permute (table-driven)
    norm_rope_kernel<<<BATCH * NHEAD * TSEQ, 128>>>(qkv, rtab, q, k, v);

    // 3) Flash attention (Br=128, 3-deep KV pipeline)
    size_t fl_smem = (size_t)FSM_FLOATS * sizeof(float);
    cudaFuncSetAttribute(flash_mma_kernel,
                         cudaFuncAttributeMaxDynamicSharedMemorySize, (int)fl_smem);
    flash_mma_kernel<<<dim3(TSEQ / ABR, BATCH * NHEAD), 256, fl_smem>>>(q, k, v, o);

    // 4) gate GEMM with fused sigmoid * attn epilogue
    mm_tf32_kernel<<<dim3(DMOD / BN, MROWS / BM), 256, gemm_smem>>>(
        xr, wgater, g, MROWS, DMOD, DMOD, 1, bgate, o);

    // 5) output GEMM
    mm_tf32_kernel<<<dim3(DMOD / BN, MROWS / BM), 256, gemm_smem>>>(
        g, woutr, out, MROWS, DMOD, DMOD, 0, nullptr, nullptr);
}

// round 8
// speedup vs baseline: 1.0836x; 1.0024x over previous
#include <cuda_runtime.h>
#include <math.h>
#include <stdint.h>

// Problem constants (fixed by setup_inputs)
#define BATCH 2
#define TSEQ  2048
#define DMOD  2048
#define NHEAD 16
#define DHEAD 128
#define MROWS (BATCH * TSEQ)        // 4096
#define QKVN  (3 * DMOD)            // 6144

// ---------------------------------------------------------------------------
// Scratch (static device globals; no runtime allocation)
// ---------------------------------------------------------------------------
__device__ float g_qkv[(size_t)MROWS * QKVN];
__device__ float g_q[(size_t)BATCH * NHEAD * TSEQ * DHEAD];
__device__ float g_k[(size_t)BATCH * NHEAD * TSEQ * DHEAD];
__device__ float g_v[(size_t)BATCH * NHEAD * TSEQ * DHEAD];
__device__ float g_o[(size_t)BATCH * NHEAD * TSEQ * DHEAD];
__device__ float g_g[(size_t)MROWS * DMOD];
// tf32-rounded copies of inputs
__device__ float g_xr[(size_t)MROWS * DMOD];
__device__ float g_wqkvr[(size_t)DMOD * QKVN];
__device__ float g_wgater[(size_t)DMOD * DMOD];
__device__ float g_woutr[(size_t)DMOD * DMOD];
// RoPE table: [t][j] -> (cos, sin), j = 0..63
__device__ float2 g_rope[(size_t)TSEQ * 64];

// ---------------------------------------------------------------------------
// Helpers
// ---------------------------------------------------------------------------
__device__ __forceinline__ uint32_t f2tf(float x) {
    uint32_t r;
    asm("cvt.rna.tf32.f32 %0, %1;" : "=r"(r) : "f"(x));
    return r;
}

__device__ __forceinline__ void mma_tf32(float* c, const uint32_t* a, const uint32_t* b) {
    asm volatile(
        "mma.sync.aligned.m16n8k8.row.col.f32.tf32.tf32.f32 "
        "{%0,%1,%2,%3},{%4,%5,%6,%7},{%8,%9},{%0,%1,%2,%3};\n"
        : "+f"(c[0]), "+f"(c[1]), "+f"(c[2]), "+f"(c[3])
        : "r"(a[0]), "r"(a[1]), "r"(a[2]), "r"(a[3]), "r"(b[0]), "r"(b[1]));
}

__device__ __forceinline__ void cpa16(void* dst, const void* src) {
    uint32_t d = (uint32_t)__cvta_generic_to_shared(dst);
    asm volatile("cp.async.cg.shared.global [%0], [%1], 16;" :: "r"(d), "l"(src));
}
#define CP_COMMIT() asm volatile("cp.async.commit_group;")
#define CP_WAIT0()  asm volatile("cp.async.wait_group 0;")
#define CP_WAIT1()  asm volatile("cp.async.wait_group 1;")
#define CP_WAIT2()  asm volatile("cp.async.wait_group 2;")

// ---------------------------------------------------------------------------
// Fused pre-pass: tf32 rounding of x, W_qkv, W_gate, W_out + RoPE table.
// One launch (keeps flash at app-launch #4 for ncu).
// ---------------------------------------------------------------------------
#define RN1 ((MROWS * DMOD) / 4)            // x      : 2097152 float4
#define RN2 ((DMOD * QKVN) / 4)             // W_qkv  : 3145728
#define RN3 ((DMOD * DMOD) / 4)             // W_gate : 1048576
#define RNTOT (RN1 + RN2 + 2 * RN3)         // 7340032
#define RNR (TSEQ * 64)                     // rope entries: 131072
#define RNALL (RNTOT + RNR)

__global__ void __launch_bounds__(256)
fused_round_kernel(const float* __restrict__ x,  float* __restrict__ xr,
                   const float* __restrict__ w1, float* __restrict__ w1r,
                   const float* __restrict__ w2, float* __restrict__ w2r,
                   const float* __restrict__ w3, float* __restrict__ w3r,
                   float2* __restrict__ rtab)
{
    int i = blockIdx.x * blockDim.x + threadIdx.x;
    if (i >= RNALL) return;
    if (i >= RNTOT) {
        int idx = i - RNTOT;
        int t = idx >> 6;
        int j = idx & 63;
        double freq = exp(-((double)j / 64.0) * 9.210340371976184);  // ln(1e4)
        double ang = (double)t * freq;
        double sd, cd;
        sincos(ang, &sd, &cd);
        rtab[idx] = make_float2((float)cd, (float)sd);
        return;
    }
    const float4* src;
    float4* dst;
    int off;
    if (i < RN1)                   { src = (const float4*)x;  dst = (float4*)xr;  off = i; }
    else if (i < RN1 + RN2)        { src = (const float4*)w1; dst = (float4*)w1r; off = i - RN1; }
    else if (i < RN1 + RN2 + RN3)  { src = (const float4*)w2; dst = (float4*)w2r; off = i - RN1 - RN2; }
    else                           { src = (const float4*)w3; dst = (float4*)w3r; off = i - RN1 - RN2 - RN3; }
    float4 v = src[off];
    v.x = __uint_as_float(f2tf(v.x));
    v.y = __uint_as_float(f2tf(v.y));
    v.z = __uint_as_float(f2tf(v.z));
    v.w = __uint_as_float(f2tf(v.w));
    dst[off] = v;
}

// ---------------------------------------------------------------------------
// tf32 GEMM: C[M,N] = A[M,K] @ B[K,N] (A,B pre-rounded to tf32 values).
// BM=BN=128, BK=16, 3-stage cp.async ring, 256 threads, warp tile 32x64.
// mode 0: plain store; mode 1: C = round_tf32(sigmoid(acc+bias[n]) * gateO)
// ---------------------------------------------------------------------------
#define BM 128
#define BN 128
#define BK 16
#define BKP (BK + 4)    // 20
#define BNP (BN + 8)    // 136
#define GST 3           // stages

#define AS(s, r, c) Ash[(size_t)(s) * BM * BKP + (r) * BKP + (c)]
#define BS(s, r, c) Bsh[(size_t)(s) * BK * BNP + (r) * BNP + (c)]

__global__ void __launch_bounds__(256, 2)
mm_tf32_kernel(const float* __restrict__ A, const float* __restrict__ B,
               float* __restrict__ C, int M, int N, int K,
               int mode, const float* __restrict__ bias,
               const float* __restrict__ gateO)
{
    extern __shared__ float gsm[];
    float* Ash = gsm;
    float* Bsh = gsm + GST * BM * BKP;

    const int bx = blockIdx.x, by = blockIdx.y;
    const int tid = threadIdx.x;
    const int lane = tid & 31;
    const int warp = tid >> 5;
    const int wm = warp >> 1;
    const int wn = warp & 1;
    const int g  = lane >> 2;
    const int tg = lane & 3;

    const int aR0 = tid >> 2;
    const int aC  = (tid & 3) << 2;
    const int bR0 = tid >> 5;
    const int bC  = (tid & 31) << 2;

    const float* Abase = A + (size_t)(by * BM) * K;
    const float* Bbase = B + (size_t)(bx * BN);

    float acc[2][8][4];
#pragma unroll
    for (int im = 0; im < 2; im++)
#pragma unroll
        for (int in = 0; in < 8; in++)
#pragma unroll
            for (int j = 0; j < 4; j++) acc[im][in][j] = 0.f;

    const int KT = K / BK;

#pragma unroll
    for (int s = 0; s < 2; s++) {
        const int k0 = s * BK;
#pragma unroll
        for (int p = 0; p < 2; p++) {
            int r = aR0 + p * 64;
            cpa16(&AS(s, r, aC), Abase + (size_t)r * K + k0 + aC);
        }
#pragma unroll
        for (int p = 0; p < 2; p++) {
            int r = bR0 + p * 8;
            cpa16(&BS(s, r, bC), Bbase + (size_t)(k0 + r) * N + bC);
        }
        CP_COMMIT();
    }

    for (int kt = 0; kt < KT; kt++) {
        const int cur = kt % GST;
        if (kt + 1 < KT) { CP_WAIT1(); } else { CP_WAIT0(); }
        __syncthreads();

        if (kt + 2 < KT) {
            const int nxt = (kt + 2) % GST;
            const int k0 = (kt + 2) * BK;
#pragma unroll
            for (int p = 0; p < 2; p++) {
                int r = aR0 + p * 64;
                cpa16(&AS(nxt, r, aC), Abase + (size_t)r * K + k0 + aC);
            }
#pragma unroll
            for (int p = 0; p < 2; p++) {
                int r = bR0 + p * 8;
                cpa16(&BS(nxt, r, bC), Bbase + (size_t)(k0 + r) * N + bC);
            }
            CP_COMMIT();
        }

#pragma unroll
        for (int ik = 0; ik < 2; ik++) {
            uint32_t afr[2][4];
#pragma unroll
            for (int im = 0; im < 2; im++) {
                int r = wm * 32 + im * 16 + g;
                int c = ik * 8 + tg;
                afr[im][0] = __float_as_uint(AS(cur, r, c));
                afr[im][1] = __float_as_uint(AS(cur, r + 8, c));
                afr[im][2] = __float_as_uint(AS(cur, r, c + 4));
                afr[im][3] = __float_as_uint(AS(cur, r + 8, c + 4));
            }
            uint32_t bfr[8][2];
#pragma unroll
            for (int in = 0; in < 8; in++) {
                int cc = wn * 64 + in * 8 + g;
                int rk = ik * 8 + tg;
                bfr[in][0] = __float_as_uint(BS(cur, rk, cc));
                bfr[in][1] = __float_as_uint(BS(cur, rk + 4, cc));
            }
#pragma unroll
            for (int im = 0; im < 2; im++)
#pragma unroll
                for (int in = 0; in < 8; in++)
                    mma_tf32(acc[im][in], afr[im], bfr[in]);
        }
    }

    if (mode == 0) {
#pragma unroll
        for (int im = 0; im < 2; im++) {
            int r = by * BM + wm * 32 + im * 16 + g;
#pragma unroll
            for (int in = 0; in < 8; in++) {
                int c = bx * BN + wn * 64 + in * 8 + 2 * tg;
                *(float2*)(C + (size_t)r * N + c) =
                    make_float2(acc[im][in][0], acc[im][in][1]);
                *(float2*)(C + (size_t)(r + 8) * N + c) =
                    make_float2(acc[im][in][2], acc[im][in][3]);
            }
        }
    } else {
#pragma unroll
        for (int im = 0; im < 2; im++) {
            int rbase = by * BM + wm * 32 + im * 16 + g;
#pragma unroll
            for (int in = 0; in < 8; in++) {
                int cbase = bx * BN + wn * 64 + in * 8 + 2 * tg;
#pragma unroll
                for (int e = 0; e < 4; e++) {
                    int r = rbase + (e >> 1) * 8;
                    int c = cbase + (e & 1);
                    int b = r >> 11;
                    int t = r & (TSEQ - 1);
                    float z = acc[im][in][e] + bias[c];
                    float gte = 1.f / (1.f + expf(-z));
                    int h = c >> 7;
                    int dd = c & (DHEAD - 1);
                    size_t oidx = (((size_t)(b * NHEAD + h)) * TSEQ + t) * DHEAD + dd;
                    C[(size_t)r * N + c] = __uint_as_float(f2tf(gte * gateO[oidx]));
                }
            }
        }
    }
}

// ---------------------------------------------------------------------------
// RMSNorm + RoPE for q,k (plus v permute); outputs tf32-rounded.
// Q is pre-scaled by 1/sqrt(d). RoPE angles from precomputed table.
// ---------------------------------------------------------------------------
__global__ void __launch_bounds__(128)
norm_rope_kernel(const float* __restrict__ qkv,
                 const float2* __restrict__ rtab,
                 float* __restrict__ Qo, float* __restrict__ Ko,
                 float* __restrict__ Vo)
{
    const int rid = blockIdx.x;
    const int t  = rid & (TSEQ - 1);
    const int bh = rid >> 11;
    const int b  = bh >> 4;
    const int h  = bh & (NHEAD - 1);
    const int i  = threadIdx.x;

    const float* row = qkv + ((size_t)(b * TSEQ + t)) * QKVN + h * DHEAD;
    float qv = row[i];
    float kv = row[DMOD + i];
    float vv = row[2 * DMOD + i];

    float q2 = qv * qv, k2 = kv * kv;
#pragma unroll
    for (int o = 16; o; o >>= 1) {
        q2 += __shfl_xor_sync(0xffffffffu, q2, o);
        k2 += __shfl_xor_sync(0xffffffffu, k2, o);
    }
    __shared__ float rq[4], rk[4];
    if ((i & 31) == 0) { rq[i >> 5] = q2; rk[i >> 5] = k2; }
    __syncthreads();
    float ssq = rq[0] + rq[1] + rq[2] + rq[3];
    float ssk = rk[0] + rk[1] + rk[2] + rk[3];
    float rnq = rsqrtf(ssq * (1.f / DHEAD) + 1e-6f);
    float rnk = rsqrtf(ssk * (1.f / DHEAD) + 1e-6f);

    __shared__ float sq[DHEAD], sk[DHEAD];
    sq[i] = qv * rnq;
    sk[i] = kv * rnk;
    __syncthreads();

    const int j = i & 63;
    float2 cs = rtab[(size_t)t * 64 + j];
    float c = cs.x, s = cs.y;

    float oq, ok;
    if (i < 64) {
        oq = sq[i] * c - sq[i + 64] * s;
        ok = sk[i] * c - sk[i + 64] * s;
    } else {
        oq = sq[i - 64] * s + sq[i] * c;
        ok = sk[i - 64] * s + sk[i] * c;
    }
    const float qscale = 0.08838834764831845f;  // 1/sqrt(128), folded into Q
    size_t oidx = ((size_t)bh * TSEQ + t) * DHEAD + i;
    Qo[oidx] = __uint_as_float(f2tf(oq * qscale));
    Ko[oidx] = __uint_as_float(f2tf(ok));
    Vo[oidx] = __uint_as_float(f2tf(vv));
}

// ---------------------------------------------------------------------------
// Flash attention (causal), tf32 mma. Br=128, Bc=64, 256 threads (8 warps).
// K and V triple-buffered with a 2-tile prefetch window (DRAM latency cover).
// Q staging overlays K buffers 0-1; P converted reg->reg via shfl (no P smem,
// no explicit tf32 rounding of P: HW reads mantissa bits [22:13] directly).
// Scale pre-folded into Q. Smem = 198 KB, 1 CTA/SM.
// ---------------------------------------------------------------------------
#define ABR 128
#define ABC 64
#define DP  132            // d + 4
#define KTF (ABR / ABC)    // 2 kv-tiles per q-tile
#define NBUF 3
#define TILEF (ABC * DP)   // 8448 floats per tile buffer
#define FSM_FLOATS (2 * NBUF * TILEF)   // 50688 floats = 202752 B

__global__ void __launch_bounds__(256, 1)
flash_mma_kernel(const float* __restrict__ Qg, const float* __restrict__ Kg,
                 const float* __restrict__ Vg, float* __restrict__ Og)
{
    extern __shared__ float fsm[];

    const int qt = (gridDim.x - 1) - blockIdx.x;   // heavy tiles first
    const int bh = blockIdx.y;
    const int tid  = threadIdx.x;
    const int lane = tid & 31;
    const int w    = tid >> 5;          // warp 0..7
    const int g    = lane >> 2;
    const int tg   = lane & 3;

    const float* Qb = Qg + (size_t)bh * TSEQ * DHEAD;
    const float* Kb = Kg + (size_t)bh * TSEQ * DHEAD;
    const float* Vb = Vg + (size_t)bh * TSEQ * DHEAD;

    const int ktmax = KTF * (qt + 1);

    // --- prologue: stage Q (128x128) into K buffers 0-1 region
#pragma unroll
    for (int p = 0; p < 16; p++) {
        int idx = tid + p * 256;
        int r = idx >> 5;
        int c = (idx & 31) << 2;
        cpa16(&fsm[r * DP + c], Qb + (size_t)(qt * ABR + r) * DHEAD + c);
    }
    CP_COMMIT();
    CP_WAIT0();
    __syncthreads();

    uint32_t qf[16][4];
    {
        int r = w * 16 + g;
#pragma unroll
        for (int ik = 0; ik < 16; ik++) {
            int c = ik * 8 + tg;
            qf[ik][0] = __float_as_uint(fsm[r * DP + c]);
            qf[ik][1] = __float_as_uint(fsm[(r + 8) * DP + c]);
            qf[ik][2] = __float_as_uint(fsm[r * DP + c + 4]);
            qf[ik][3] = __float_as_uint(fsm[(r + 8) * DP + c + 4]);
        }
    }
    __syncthreads();   // all warps done with Q before K(0)/K(1) overwrite it

    // prefetch tiles 0 and 1 (one group each: {K,V})
#pragma unroll
    for (int s = 0; s < 2; s++) {
        if (s < ktmax) {
            float* ks = fsm + s * TILEF;
            float* vs = fsm + (NBUF + s) * TILEF;
            const float* kp = Kb + (size_t)s * ABC * DHEAD;
            const float* vp = Vb + (size_t)s * ABC * DHEAD;
#pragma unroll
            for (int p = 0; p < 8; p++) {
                int idx = tid + p * 256;
                int r = idx >> 5;
                int c = (idx & 31) << 2;
                cpa16(&ks[r * DP + c], kp + (size_t)r * DHEAD + c);
                cpa16(&vs[r * DP + c], vp + (size_t)r * DHEAD + c);
            }
            CP_COMMIT();
        }
    }

    float oacc[16][4];
#pragma unroll
    for (int in = 0; in < 16; in++)
#pragma unroll
        for (int j = 0; j < 4; j++) oacc[in][j] = 0.f;
    float m_i[2] = {-INFINITY, -INFINITY};
    float l_i[2] = {0.f, 0.f};

    const int rlo = qt * ABR + w * 16 + g;

    for (int kt = 0; kt < ktmax; kt++) {
        // prefetch tile kt+2 into buffer (kt+2)%3 (freed by prev-iter sync)
        if (kt + 2 < ktmax) {
            int s = (kt + 2) % NBUF;
            float* ks = fsm + s * TILEF;
            float* vs = fsm + (NBUF + s) * TILEF;
            const float* kp = Kb + (size_t)(kt + 2) * ABC * DHEAD;
            const float* vp = Vb + (size_t)(kt + 2) * ABC * DHEAD;
#pragma unroll
            for (int p = 0; p < 8; p++) {
                int idx = tid + p * 256;
                int r = idx >> 5;
                int c = (idx & 31) << 2;
                cpa16(&ks[r * DP + c], kp + (size_t)r * DHEAD + c);
                cpa16(&vs[r * DP + c], vp + (size_t)r * DHEAD + c);
            }
            CP_COMMIT();
            CP_WAIT2();    // tile kt complete; kt+1, kt+2 in flight
        } else if (kt + 1 < ktmax) {
            CP_WAIT1();    // tile kt complete; kt+1 in flight
        } else {
            CP_WAIT0();
        }
        __syncthreads();

        const float* Ksc = fsm + (kt % NBUF) * TILEF;
        const float* Vsc = fsm + (NBUF + kt % NBUF) * TILEF;

        // S = Q @ K^T  (warp: 16 x 64; 8 n-atoms)
        float sacc[8][4];
#pragma unroll
        for (int in = 0; in < 8; in++)
#pragma unroll
            for (int j = 0; j < 4; j++) sacc[in][j] = 0.f;

#pragma unroll
        for (int ik = 0; ik < 16; ik++) {
#pragma unroll
            for (int in = 0; in < 8; in++) {
                uint32_t bf[2];
                int srow = in * 8 + g;
                int dcol = ik * 8 + tg;
                bf[0] = __float_as_uint(Ksc[srow * DP + dcol]);
                bf[1] = __float_as_uint(Ksc[srow * DP + dcol + 4]);
                mma_tf32(sacc[in], qf[ik], bf);
            }
        }

        // causal mask (band tiles only)
        if (kt >= KTF * qt) {
#pragma unroll
            for (int in = 0; in < 8; in++) {
                int cbase = kt * ABC + in * 8 + 2 * tg;
#pragma unroll
                for (int j = 0; j < 4; j++) {
                    int cg = cbase + (j & 1);
                    int rg = rlo + (j >> 1) * 8;
                    if (cg > rg) sacc[in][j] = -INFINITY;
                }
            }
        }

        // online softmax per owned row (rr=0: row g ; rr=1: row g+8)
        float alpha[2];
#pragma unroll
        for (int rr = 0; rr < 2; rr++) {
            float pm = -INFINITY;
#pragma unroll
            for (int in = 0; in < 8; in++) {
                pm = fmaxf(pm, sacc[in][2 * rr]);
                pm = fmaxf(pm, sacc[in][2 * rr + 1]);
            }
            pm = fmaxf(pm, __shfl_xor_sync(0xffffffffu, pm, 1));
            pm = fmaxf(pm, __shfl_xor_sync(0xffffffffu, pm, 2));
            float mnew = fmaxf(m_i[rr], pm);
            float ps = 0.f;
#pragma unroll
            for (int in = 0; in < 8; in++) {
                float e0 = __expf(sacc[in][2 * rr]     - mnew);
                float e1 = __expf(sacc[in][2 * rr + 1] - mnew);
                sacc[in][2 * rr] = e0;
                sacc[in][2 * rr + 1] = e1;
                ps += e0 + e1;
            }
            ps += __shfl_xor_sync(0xffffffffu, ps, 1);
            ps += __shfl_xor_sync(0xffffffffu, ps, 2);
            alpha[rr] = __expf(m_i[rr] - mnew);
            l_i[rr] = l_i[rr] * alpha[rr] + ps;
            m_i[rr] = mnew;
        }
#pragma unroll
        for (int in = 0; in < 16; in++) {
            oacc[in][0] *= alpha[0]; oacc[in][1] *= alpha[0];
            oacc[in][2] *= alpha[1]; oacc[in][3] *= alpha[1];
        }

        // O += P @ V  (P converted C-frag -> A-frag via shfl; raw fp32 bits
        // fed to tf32 mma = truncation, error ~2^-10 on P, acceptable)
#pragma unroll
        for (int ik = 0; ik < 8; ik++) {
            const int srcA = (lane & 28) | (tg >> 1);
            const int srcB = srcA + 2;
            const bool odd = (tg & 1) != 0;
            float e0 = __shfl_sync(0xffffffffu, sacc[ik][0], srcA);
            float e1 = __shfl_sync(0xffffffffu, sacc[ik][1], srcA);
            float e2 = __shfl_sync(0xffffffffu, sacc[ik][2], srcA);
            float e3 = __shfl_sync(0xffffffffu, sacc[ik][3], srcA);
            float f0 = __shfl_sync(0xffffffffu, sacc[ik][0], srcB);
            float f1 = __shfl_sync(0xffffffffu, sacc[ik][1], srcB);
            float f2 = __shfl_sync(0xffffffffu, sacc[ik][2], srcB);
            float f3 = __shfl_sync(0xffffffffu, sacc[ik][3], srcB);
            uint32_t af[4];
            af[0] = __float_as_uint(odd ? e1 : e0);   // P[g][tg]
            af[1] = __float_as_uint(odd ? e3 : e2);   // P[g+8][tg]
            af[2] = __float_as_uint(odd ? f1 : f0);   // P[g][tg+4]
            af[3] = __float_as_uint(odd ? f3 : f2);   // P[g+8][tg+4]
#pragma unroll
            for (int in = 0; in < 16; in++) {
                uint32_t bf[2];
                int krow = ik * 8 + tg;
                int dcol = in * 8 + g;
                bf[0] = __float_as_uint(Vsc[krow * DP + dcol]);
                bf[1] = __float_as_uint(Vsc[(krow + 4) * DP + dcol]);
                mma_tf32(oacc[in], af, bf);
            }
        }
        __syncthreads();   // all warps done with buffer kt%3 before refill
    }

    // epilogue
    float inv0 = 1.f / l_i[0];
    float inv1 = 1.f / l_i[1];
    {
        int r = qt * ABR + w * 16 + g;
        float* Ob = Og + (size_t)bh * TSEQ * DHEAD;
#pragma unroll
        for (int in = 0; in < 16; in++) {
            int c = in * 8 + 2 * tg;
            *(float2*)(Ob + (size_t)r * DHEAD + c) =
                make_float2(oacc[in][0] * inv0, oacc[in][1] * inv0);
            *(float2*)(Ob + (size_t)(r + 8) * DHEAD + c) =
                make_float2(oacc[in][2] * inv1, oacc[in][3] * inv1);
        }
    }
}

// ---------------------------------------------------------------------------
// Host launcher
// ---------------------------------------------------------------------------
extern "C" void kernel_launch(void* const* d_in, const int* in_sizes, int n_in,
                              void* d_out, int out_size)
{
    const float* x     = (const float*)d_in[0];
    const float* Wqkv  = (const float*)d_in[1];
    const float* Wout  = (const float*)d_in[2];
    const float* Wgate = (const float*)d_in[3];
    const float* bgate = (const float*)d_in[4];
    float* out = (float*)d_out;

    float *qkv, *q, *k, *v, *o, *g, *xr, *wqkvr, *wgater, *woutr;
    float2* rtab;
    cudaGetSymbolAddress((void**)&qkv,    g_qkv);
    cudaGetSymbolAddress((void**)&q,      g_q);
    cudaGetSymbolAddress((void**)&k,      g_k);
    cudaGetSymbolAddress((void**)&v,      g_v);
    cudaGetSymbolAddress((void**)&o,      g_o);
    cudaGetSymbolAddress((void**)&g,      g_g);
    cudaGetSymbolAddress((void**)&xr,     g_xr);
    cudaGetSymbolAddress((void**)&wqkvr,  g_wqkvr);
    cudaGetSymbolAddress((void**)&wgater, g_wgater);
    cudaGetSymbolAddress((void**)&woutr,  g_woutr);
    cudaGetSymbolAddress((void**)&rtab,   g_rope);

    // 0) fused tf32 pre-round + RoPE table (ONE launch)
    fused_round_kernel<<<(RNALL + 255) / 256, 256>>>(
        x, xr, Wqkv, wqkvr, Wgate, wgater, Wout, woutr, rtab);

    size_t gemm_smem = (size_t)(GST * BM * BKP + GST * BK * BNP) * sizeof(float);
    cudaFuncSetAttribute(mm_tf32_kernel,
                         cudaFuncAttributeMaxDynamicSharedMemorySize, (int)gemm_smem);

    // 1) QKV GEMM (launch #2)
    mm_tf32_kernel<<<dim3(QKVN / BN, MROWS / BM), 256, gemm_smem>>>(
        xr, wqkvr, qkv, MROWS, QKVN, DMOD, 0, nullptr, nullptr);

    // 2) RMSNorm + RoPE + permute (launch #3)
    norm_rope_kernel<<<BATCH * NHEAD * TSEQ, 128>>>(qkv, rtab, q, k, v);

    // 3) Flash attention (launch #4 -> ncu target)
    size_t fl_smem = (size_t)FSM_FLOATS * sizeof(float);
    cudaFuncSetAttribute(flash_mma_kernel,
                         cudaFuncAttributeMaxDynamicSharedMemorySize, (int)fl_smem);
    flash_mma_kernel<<<dim3(TSEQ / ABR, BATCH * NHEAD), 256, fl_smem>>>(q, k, v, o);

    // 4) gate GEMM with fused sigmoid * attn epilogue (launch #5)
    mm_tf32_kernel<<<dim3(DMOD / BN, MROWS / BM), 256, gemm_smem>>>(
        xr, wgater, g, MROWS, DMOD, DMOD, 1, bgate, o);

    // 5) output GEMM (launch #6)
    mm_tf32_kernel<<<dim3(DMOD / BN, MROWS / BM), 256, gemm_smem>>>(
        g, woutr, out, MROWS, DMOD, DMOD, 0, nullptr, nullptr);
}

// round 10
// speedup vs baseline: 1.1178x; 1.0315x over previous
#include <cuda_runtime.h>
#include <math.h>
#include <stdint.h>

// Problem constants (fixed by setup_inputs)
#define BATCH 2
#define TSEQ  2048
#define DMOD  2048
#define NHEAD 16
#define DHEAD 128
#define MROWS (BATCH * TSEQ)        // 4096
#define QKVN  (3 * DMOD)            // 6144

// ---------------------------------------------------------------------------
// Scratch (static device globals; no runtime allocation)
// ---------------------------------------------------------------------------
__device__ float g_qkv[(size_t)MROWS * QKVN];
__device__ float g_q[(size_t)BATCH * NHEAD * TSEQ * DHEAD];
__device__ float g_k[(size_t)BATCH * NHEAD * TSEQ * DHEAD];
__device__ float g_v[(size_t)BATCH * NHEAD * TSEQ * DHEAD];
__device__ float g_o[(size_t)MROWS * DMOD];     // attn out, [B,T,D] layout!
__device__ float g_g[(size_t)MROWS * DMOD];
// tf32-rounded copies of inputs
__device__ float g_xr[(size_t)MROWS * DMOD];
__device__ float g_wqkvr[(size_t)DMOD * QKVN];
__device__ float g_wgater[(size_t)DMOD * DMOD];
__device__ float g_woutr[(size_t)DMOD * DMOD];
// RoPE table: [t][j] -> (cos, sin), j = 0..63
__device__ float2 g_rope[(size_t)TSEQ * 64];

// ---------------------------------------------------------------------------
// Helpers
// ---------------------------------------------------------------------------
__device__ __forceinline__ uint32_t f2tf(float x) {
    uint32_t r;
    asm("cvt.rna.tf32.f32 %0, %1;" : "=r"(r) : "f"(x));
    return r;
}

__device__ __forceinline__ void mma_tf32(float* c, const uint32_t* a, const uint32_t* b) {
    asm volatile(
        "mma.sync.aligned.m16n8k8.row.col.f32.tf32.tf32.f32 "
        "{%0,%1,%2,%3},{%4,%5,%6,%7},{%8,%9},{%0,%1,%2,%3};\n"
        : "+f"(c[0]), "+f"(c[1]), "+f"(c[2]), "+f"(c[3])
        : "r"(a[0]), "r"(a[1]), "r"(a[2]), "r"(a[3]), "r"(b[0]), "r"(b[1]));
}

__device__ __forceinline__ void cpa16(void* dst, const void* src) {
    uint32_t d = (uint32_t)__cvta_generic_to_shared(dst);
    asm volatile("cp.async.cg.shared.global [%0], [%1], 16;" :: "r"(d), "l"(src));
}
#define CP_COMMIT() asm volatile("cp.async.commit_group;")
#define CP_WAIT0()  asm volatile("cp.async.wait_group 0;")
#define CP_WAIT1()  asm volatile("cp.async.wait_group 1;")
#define CP_WAIT2()  asm volatile("cp.async.wait_group 2;")

// ---------------------------------------------------------------------------
// Fused pre-pass: tf32 rounding of x, W_qkv, W_gate, W_out + RoPE table.
// ---------------------------------------------------------------------------
#define RN1 ((MROWS * DMOD) / 4)
#define RN2 ((DMOD * QKVN) / 4)
#define RN3 ((DMOD * DMOD) / 4)
#define RNTOT (RN1 + RN2 + 2 * RN3)
#define RNR (TSEQ * 64)
#define RNALL (RNTOT + RNR)

__global__ void __launch_bounds__(256)
fused_round_kernel(const float* __restrict__ x,  float* __restrict__ xr,
                   const float* __restrict__ w1, float* __restrict__ w1r,
                   const float* __restrict__ w2, float* __restrict__ w2r,
                   const float* __restrict__ w3, float* __restrict__ w3r,
                   float2* __restrict__ rtab)
{
    int i = blockIdx.x * blockDim.x + threadIdx.x;
    if (i >= RNALL) return;
    if (i >= RNTOT) {
        int idx = i - RNTOT;
        int t = idx >> 6;
        int j = idx & 63;
        double freq = exp(-((double)j / 64.0) * 9.210340371976184);  // ln(1e4)
        double ang = (double)t * freq;
        double sd, cd;
        sincos(ang, &sd, &cd);
        rtab[idx] = make_float2((float)cd, (float)sd);
        return;
    }
    const float4* src;
    float4* dst;
    int off;
    if (i < RN1)                   { src = (const float4*)x;  dst = (float4*)xr;  off = i; }
    else if (i < RN1 + RN2)        { src = (const float4*)w1; dst = (float4*)w1r; off = i - RN1; }
    else if (i < RN1 + RN2 + RN3)  { src = (const float4*)w2; dst = (float4*)w2r; off = i - RN1 - RN2; }
    else                           { src = (const float4*)w3; dst = (float4*)w3r; off = i - RN1 - RN2 - RN3; }
    float4 v = src[off];
    v.x = __uint_as_float(f2tf(v.x));
    v.y = __uint_as_float(f2tf(v.y));
    v.z = __uint_as_float(f2tf(v.z));
    v.w = __uint_as_float(f2tf(v.w));
    dst[off] = v;
}

// ---------------------------------------------------------------------------
// tf32 GEMM: C[M,N] = A[M,K] @ B[K,N] (A,B pre-rounded to tf32 values).
// BM=BN=128, BK=16, 3-stage cp.async ring, 256 threads, warp tile 32x64.
// mode 0: plain store
// mode 1: C = round_tf32(sigmoid(acc+bias[n]) * gateO[m*N+n])  (coalesced)
// ---------------------------------------------------------------------------
#define BM 128
#define BN 128
#define BK 16
#define BKP (BK + 4)    // 20
#define BNP (BN + 8)    // 136
#define GST 3           // stages

#define AS(s, r, c) Ash[(size_t)(s) * BM * BKP + (r) * BKP + (c)]
#define BS(s, r, c) Bsh[(size_t)(s) * BK * BNP + (r) * BNP + (c)]

__global__ void __launch_bounds__(256, 2)
mm_tf32_kernel(const float* __restrict__ A, const float* __restrict__ B,
               float* __restrict__ C, int M, int N, int K,
               int mode, const float* __restrict__ bias,
               const float* __restrict__ gateO)
{
    extern __shared__ float gsm[];
    float* Ash = gsm;
    float* Bsh = gsm + GST * BM * BKP;

    const int bx = blockIdx.x, by = blockIdx.y;
    const int tid = threadIdx.x;
    const int lane = tid & 31;
    const int warp = tid >> 5;
    const int wm = warp >> 1;
    const int wn = warp & 1;
    const int g  = lane >> 2;
    const int tg = lane & 3;

    const int aR0 = tid >> 2;
    const int aC  = (tid & 3) << 2;
    const int bR0 = tid >> 5;
    const int bC  = (tid & 31) << 2;

    const float* Abase = A + (size_t)(by * BM) * K;
    const float* Bbase = B + (size_t)(bx * BN);

    float acc[2][8][4];
#pragma unroll
    for (int im = 0; im < 2; im++)
#pragma unroll
        for (int in = 0; in < 8; in++)
#pragma unroll
            for (int j = 0; j < 4; j++) acc[im][in][j] = 0.f;

    const int KT = K / BK;

#pragma unroll
    for (int s = 0; s < 2; s++) {
        const int k0 = s * BK;
#pragma unroll
        for (int p = 0; p < 2; p++) {
            int r = aR0 + p * 64;
            cpa16(&AS(s, r, aC), Abase + (size_t)r * K + k0 + aC);
        }
#pragma unroll
        for (int p = 0; p < 2; p++) {
            int r = bR0 + p * 8;
            cpa16(&BS(s, r, bC), Bbase + (size_t)(k0 + r) * N + bC);
        }
        CP_COMMIT();
    }

    for (int kt = 0; kt < KT; kt++) {
        const int cur = kt % GST;
        if (kt + 1 < KT) { CP_WAIT1(); } else { CP_WAIT0(); }
        __syncthreads();

        if (kt + 2 < KT) {
            const int nxt = (kt + 2) % GST;
            const int k0 = (kt + 2) * BK;
#pragma unroll
            for (int p = 0; p < 2; p++) {
                int r = aR0 + p * 64;
                cpa16(&AS(nxt, r, aC), Abase + (size_t)r * K + k0 + aC);
            }
#pragma unroll
            for (int p = 0; p < 2; p++) {
                int r = bR0 + p * 8;
                cpa16(&BS(nxt, r, bC), Bbase + (size_t)(k0 + r) * N + bC);
            }
            CP_COMMIT();
        }

#pragma unroll
        for (int ik = 0; ik < 2; ik++) {
            uint32_t afr[2][4];
#pragma unroll
            for (int im = 0; im < 2; im++) {
                int r = wm * 32 + im * 16 + g;
                int c = ik * 8 + tg;
                afr[im][0] = __float_as_uint(AS(cur, r, c));
                afr[im][1] = __float_as_uint(AS(cur, r + 8, c));
                afr[im][2] = __float_as_uint(AS(cur, r, c + 4));
                afr[im][3] = __float_as_uint(AS(cur, r + 8, c + 4));
            }
            uint32_t bfr[8][2];
#pragma unroll
            for (int in = 0; in < 8; in++) {
                int cc = wn * 64 + in * 8 + g;
                int rk = ik * 8 + tg;
                bfr[in][0] = __float_as_uint(BS(cur, rk, cc));
                bfr[in][1] = __float_as_uint(BS(cur, rk + 4, cc));
            }
#pragma unroll
            for (int im = 0; im < 2; im++)
#pragma unroll
                for (int in = 0; in < 8; in++)
                    mma_tf32(acc[im][in], afr[im], bfr[in]);
        }
    }

    if (mode == 0) {
#pragma unroll
        for (int im = 0; im < 2; im++) {
            int r = by * BM + wm * 32 + im * 16 + g;
#pragma unroll
            for (int in = 0; in < 8; in++) {
                int c = bx * BN + wn * 64 + in * 8 + 2 * tg;
                *(float2*)(C + (size_t)r * N + c) =
                    make_float2(acc[im][in][0], acc[im][in][1]);
                *(float2*)(C + (size_t)(r + 8) * N + c) =
                    make_float2(acc[im][in][2], acc[im][in][3]);
            }
        }
    } else {
        // gateO is in [B,T,D] layout -> index m*N + n, fully coalesced.
#pragma unroll
        for (int im = 0; im < 2; im++) {
            int r0 = by * BM + wm * 32 + im * 16 + g;
            int r1 = r0 + 8;
            // hoist all gateO/bias loads so their latency overlaps the expf chain
            float2 bv[8], go0[8], go1[8];
#pragma unroll
            for (int in = 0; in < 8; in++) {
                int c = bx * BN + wn * 64 + in * 8 + 2 * tg;
                bv[in]  = *(const float2*)(bias + c);
                go0[in] = *(const float2*)(gateO + (size_t)r0 * N + c);
                go1[in] = *(const float2*)(gateO + (size_t)r1 * N + c);
            }
#pragma unroll
            for (int in = 0; in < 8; in++) {
                int c = bx * BN + wn * 64 + in * 8 + 2 * tg;
                float s00 = 1.f / (1.f + __expf(-(acc[im][in][0] + bv[in].x)));
                float s01 = 1.f / (1.f + __expf(-(acc[im][in][1] + bv[in].y)));
                float s10 = 1.f / (1.f + __expf(-(acc[im][in][2] + bv[in].x)));
                float s11 = 1.f / (1.f + __expf(-(acc[im][in][3] + bv[in].y)));
                *(float2*)(C + (size_t)r0 * N + c) = make_float2(
                    __uint_as_float(f2tf(s00 * go0[in].x)),
                    __uint_as_float(f2tf(s01 * go0[in].y)));
                *(float2*)(C + (size_t)r1 * N + c) = make_float2(
                    __uint_as_float(f2tf(s10 * go1[in].x)),
                    __uint_as_float(f2tf(s11 * go1[in].y)));
            }
        }
    }
}

// ---------------------------------------------------------------------------
// RMSNorm + RoPE for q,k (plus v permute); outputs tf32-rounded.
// Q is pre-scaled by 1/sqrt(d). RoPE angles from precomputed table.
// ---------------------------------------------------------------------------
__global__ void __launch_bounds__(128)
norm_rope_kernel(const float* __restrict__ qkv,
                 const float2* __restrict__ rtab,
                 float* __restrict__ Qo, float* __restrict__ Ko,
                 float* __restrict__ Vo)
{
    const int rid = blockIdx.x;
    const int t  = rid & (TSEQ - 1);
    const int bh = rid >> 11;
    const int b  = bh >> 4;
    const int h  = bh & (NHEAD - 1);
    const int i  = threadIdx.x;

    const float* row = qkv + ((size_t)(b * TSEQ + t)) * QKVN + h * DHEAD;
    float qv = row[i];
    float kv = row[DMOD + i];
    float vv = row[2 * DMOD + i];

    float q2 = qv * qv, k2 = kv * kv;
#pragma unroll
    for (int o = 16; o; o >>= 1) {
        q2 += __shfl_xor_sync(0xffffffffu, q2, o);
        k2 += __shfl_xor_sync(0xffffffffu, k2, o);
    }
    __shared__ float rq[4], rk[4];
    if ((i & 31) == 0) { rq[i >> 5] = q2; rk[i >> 5] = k2; }
    __syncthreads();
    float ssq = rq[0] + rq[1] + rq[2] + rq[3];
    float ssk = rk[0] + rk[1] + rk[2] + rk[3];
    float rnq = rsqrtf(ssq * (1.f / DHEAD) + 1e-6f);
    float rnk = rsqrtf(ssk * (1.f / DHEAD) + 1e-6f);

    __shared__ float sq[DHEAD], sk[DHEAD];
    sq[i] = qv * rnq;
    sk[i] = kv * rnk;
    __syncthreads();

    const int j = i & 63;
    float2 cs = rtab[(size_t)t * 64 + j];
    float c = cs.x, s = cs.y;

    float oq, ok;
    if (i < 64) {
        oq = sq[i] * c - sq[i + 64] * s;
        ok = sk[i] * c - sk[i + 64] * s;
    } else {
        oq = sq[i - 64] * s + sq[i] * c;
        ok = sk[i - 64] * s + sk[i] * c;
    }
    const float qscale = 0.08838834764831845f;  // 1/sqrt(128), folded into Q
    size_t oidx = ((size_t)bh * TSEQ + t) * DHEAD + i;
    Qo[oidx] = __uint_as_float(f2tf(oq * qscale));
    Ko[oidx] = __uint_as_float(f2tf(ok));
    Vo[oidx] = __uint_as_float(f2tf(vv));
}

// ---------------------------------------------------------------------------
// Flash attention (causal), tf32 mma. Br=128, Bc=64, 256 threads (8 warps).
// K and V triple-buffered with a 2-tile prefetch window. Q staging overlays
// K buffers 0-1; P converted reg->reg via shfl. Scale pre-folded into Q.
// O is written in [B,T,D] layout (permute fused -> coalesced gate epilogue).
// ---------------------------------------------------------------------------
#define ABR 128
#define ABC 64
#define DP  132            // d + 4
#define KTF (ABR / ABC)    // 2 kv-tiles per q-tile
#define NBUF 3
#define TILEF (ABC * DP)   // 8448 floats per tile buffer
#define FSM_FLOATS (2 * NBUF * TILEF)   // 50688 floats = 202752 B

__global__ void __launch_bounds__(256, 1)
flash_mma_kernel(const float* __restrict__ Qg, const float* __restrict__ Kg,
                 const float* __restrict__ Vg, float* __restrict__ Og)
{
    extern __shared__ float fsm[];

    const int qt = (gridDim.x - 1) - blockIdx.x;   // heavy tiles first
    const int bh = blockIdx.y;
    const int tid  = threadIdx.x;
    const int lane = tid & 31;
    const int w    = tid >> 5;          // warp 0..7
    const int g    = lane >> 2;
    const int tg   = lane & 3;

    const float* Qb = Qg + (size_t)bh * TSEQ * DHEAD;
    const float* Kb = Kg + (size_t)bh * TSEQ * DHEAD;
    const float* Vb = Vg + (size_t)bh * TSEQ * DHEAD;

    const int ktmax = KTF * (qt + 1);

    // --- prologue: stage Q (128x128) into K buffers 0-1 region
#pragma unroll
    for (int p = 0; p < 16; p++) {
        int idx = tid + p * 256;
        int r = idx >> 5;
        int c = (idx & 31) << 2;
        cpa16(&fsm[r * DP + c], Qb + (size_t)(qt * ABR + r) * DHEAD + c);
    }
    CP_COMMIT();
    CP_WAIT0();
    __syncthreads();

    uint32_t qf[16][4];
    {
        int r = w * 16 + g;
#pragma unroll
        for (int ik = 0; ik < 16; ik++) {
            int c = ik * 8 + tg;
            qf[ik][0] = __float_as_uint(fsm[r * DP + c]);
            qf[ik][1] = __float_as_uint(fsm[(r + 8) * DP + c]);
            qf[ik][2] = __float_as_uint(fsm[r * DP + c + 4]);
            qf[ik][3] = __float_as_uint(fsm[(r + 8) * DP + c + 4]);
        }
    }
    __syncthreads();   // all warps done with Q before K(0)/K(1) overwrite it

    // prefetch tiles 0 and 1 (one group each: {K,V})
#pragma unroll
    for (int s = 0; s < 2; s++) {
        if (s < ktmax) {
            float* ks = fsm + s * TILEF;
            float* vs = fsm + (NBUF + s) * TILEF;
            const float* kp = Kb + (size_t)s * ABC * DHEAD;
            const float* vp = Vb + (size_t)s * ABC * DHEAD;
#pragma unroll
            for (int p = 0; p < 8; p++) {
                int idx = tid + p * 256;
                int r = idx >> 5;
                int c = (idx & 31) << 2;
                cpa16(&ks[r * DP + c], kp + (size_t)r * DHEAD + c);
                cpa16(&vs[r * DP + c], vp + (size_t)r * DHEAD + c);
            }
            CP_COMMIT();
        }
    }

    float oacc[16][4];
#pragma unroll
    for (int in = 0; in < 16; in++)
#pragma unroll
        for (int j = 0; j < 4; j++) oacc[in][j] = 0.f;
    float m_i[2] = {-INFINITY, -INFINITY};
    float l_i[2] = {0.f, 0.f};

    const int rlo = qt * ABR + w * 16 + g;

    for (int kt = 0; kt < ktmax; kt++) {
        if (kt + 2 < ktmax) {
            int s = (kt + 2) % NBUF;
            float* ks = fsm + s * TILEF;
            float* vs = fsm + (NBUF + s) * TILEF;
            const float* kp = Kb + (size_t)(kt + 2) * ABC * DHEAD;
            const float* vp = Vb + (size_t)(kt + 2) * ABC * DHEAD;
#pragma unroll
            for (int p = 0; p < 8; p++) {
                int idx = tid + p * 256;
                int r = idx >> 5;
                int c = (idx & 31) << 2;
                cpa16(&ks[r * DP + c], kp + (size_t)r * DHEAD + c);
                cpa16(&vs[r * DP + c], vp + (size_t)r * DHEAD + c);
            }
            CP_COMMIT();
            CP_WAIT2();
        } else if (kt + 1 < ktmax) {
            CP_WAIT1();
        } else {
            CP_WAIT0();
        }
        __syncthreads();

        const float* Ksc = fsm + (kt % NBUF) * TILEF;
        const float* Vsc = fsm + (NBUF + kt % NBUF) * TILEF;

        // S = Q @ K^T  (warp: 16 x 64; 8 n-atoms)
        float sacc[8][4];
#pragma unroll
        for (int in = 0; in < 8; in++)
#pragma unroll
            for (int j = 0; j < 4; j++) sacc[in][j] = 0.f;

#pragma unroll
        for (int ik = 0; ik < 16; ik++) {
#pragma unroll
            for (int in = 0; in < 8; in++) {
                uint32_t bf[2];
                int srow = in * 8 + g;
                int dcol = ik * 8 + tg;
                bf[0] = __float_as_uint(Ksc[srow * DP + dcol]);
                bf[1] = __float_as_uint(Ksc[srow * DP + dcol + 4]);
                mma_tf32(sacc[in], qf[ik], bf);
            }
        }

        // causal mask (band tiles only)
        if (kt >= KTF * qt) {
#pragma unroll
            for (int in = 0; in < 8; in++) {
                int cbase = kt * ABC + in * 8 + 2 * tg;
#pragma unroll
                for (int j = 0; j < 4; j++) {
                    int cg = cbase + (j & 1);
                    int rg = rlo + (j >> 1) * 8;
                    if (cg > rg) sacc[in][j] = -INFINITY;
                }
            }
        }

        // online softmax per owned row (rr=0: row g ; rr=1: row g+8)
        float alpha[2];
#pragma unroll
        for (int rr = 0; rr < 2; rr++) {
            float pm = -INFINITY;
#pragma unroll
            for (int in = 0; in < 8; in++) {
                pm = fmaxf(pm, sacc[in][2 * rr]);
                pm = fmaxf(pm, sacc[in][2 * rr + 1]);
            }
            pm = fmaxf(pm, __shfl_xor_sync(0xffffffffu, pm, 1));
            pm = fmaxf(pm, __shfl_xor_sync(0xffffffffu, pm, 2));
            float mnew = fmaxf(m_i[rr], pm);
            float ps = 0.f;
#pragma unroll
            for (int in = 0; in < 8; in++) {
                float e0 = __expf(sacc[in][2 * rr]     - mnew);
                float e1 = __expf(sacc[in][2 * rr + 1] - mnew);
                sacc[in][2 * rr] = e0;
                sacc[in][2 * rr + 1] = e1;
                ps += e0 + e1;
            }
            ps += __shfl_xor_sync(0xffffffffu, ps, 1);
            ps += __shfl_xor_sync(0xffffffffu, ps, 2);
            alpha[rr] = __expf(m_i[rr] - mnew);
            l_i[rr] = l_i[rr] * alpha[rr] + ps;
            m_i[rr] = mnew;
        }
#pragma unroll
        for (int in = 0; in < 16; in++) {
            oacc[in][0] *= alpha[0]; oacc[in][1] *= alpha[0];
            oacc[in][2] *= alpha[1]; oacc[in][3] *= alpha[1];
        }

        // O += P @ V  (P converted C-frag -> A-frag via shfl; raw fp32 bits)
#pragma unroll
        for (int ik = 0; ik < 8; ik++) {
            const int srcA = (lane & 28) | (tg >> 1);
            const int srcB = srcA + 2;
            const bool odd = (tg & 1) != 0;
            float e0 = __shfl_sync(0xffffffffu, sacc[ik][0], srcA);
            float e1 = __shfl_sync(0xffffffffu, sacc[ik][1], srcA);
            float e2 = __shfl_sync(0xffffffffu, sacc[ik][2], srcA);
            float e3 = __shfl_sync(0xffffffffu, sacc[ik][3], srcA);
            float f0 = __shfl_sync(0xffffffffu, sacc[ik][0], srcB);
            float f1 = __shfl_sync(0xffffffffu, sacc[ik][1], srcB);
            float f2 = __shfl_sync(0xffffffffu, sacc[ik][2], srcB);
            float f3 = __shfl_sync(0xffffffffu, sacc[ik][3], srcB);
            uint32_t af[4];
            af[0] = __float_as_uint(odd ? e1 : e0);   // P[g][tg]
            af[1] = __float_as_uint(odd ? e3 : e2);   // P[g+8][tg]
            af[2] = __float_as_uint(odd ? f1 : f0);   // P[g][tg+4]
            af[3] = __float_as_uint(odd ? f3 : f2);   // P[g+8][tg+4]
#pragma unroll
            for (int in = 0; in < 16; in++) {
                uint32_t bf[2];
                int krow = ik * 8 + tg;
                int dcol = in * 8 + g;
                bf[0] = __float_as_uint(Vsc[krow * DP + dcol]);
                bf[1] = __float_as_uint(Vsc[(krow + 4) * DP + dcol]);
                mma_tf32(oacc[in], af, bf);
            }
        }
        __syncthreads();   // all warps done with buffer kt%3 before refill
    }

    // epilogue: write O in [B,T,D] layout (fused permute)
    float inv0 = 1.f / l_i[0];
    float inv1 = 1.f / l_i[1];
    {
        const int b = bh >> 4;
        const int h = bh & (NHEAD - 1);
        const int t0 = qt * ABR + w * 16 + g;
        float* O0 = Og + ((size_t)(b * TSEQ + t0)     ) * DMOD + h * DHEAD;
        float* O1 = Og + ((size_t)(b * TSEQ + t0 + 8) ) * DMOD + h * DHEAD;
#pragma unroll
        for (int in = 0; in < 16; in++) {
            int c = in * 8 + 2 * tg;
            *(float2*)(O0 + c) =
                make_float2(oacc[in][0] * inv0, oacc[in][1] * inv0);
            *(float2*)(O1 + c) =
                make_float2(oacc[in][2] * inv1, oacc[in][3] * inv1);
        }
    }
}

// ---------------------------------------------------------------------------
// Host launcher
// ---------------------------------------------------------------------------
extern "C" void kernel_launch(void* const* d_in, const int* in_sizes, int n_in,
                              void* d_out, int out_size)
{
    const float* x     = (const float*)d_in[0];
    const float* Wqkv  = (const float*)d_in[1];
    const float* Wout  = (const float*)d_in[2];
    const float* Wgate = (const float*)d_in[3];
    const float* bgate = (const float*)d_in[4];
    float* out = (float*)d_out;

    float *qkv, *q, *k, *v, *o, *g, *xr, *wqkvr, *wgater, *woutr;
    float2* rtab;
    cudaGetSymbolAddress((void**)&qkv,    g_qkv);
    cudaGetSymbolAddress((void**)&q,      g_q);
    cudaGetSymbolAddress((void**)&k,      g_k);
    cudaGetSymbolAddress((void**)&v,      g_v);
    cudaGetSymbolAddress((void**)&o,      g_o);
    cudaGetSymbolAddress((void**)&g,      g_g);
    cudaGetSymbolAddress((void**)&xr,     g_xr);
    cudaGetSymbolAddress((void**)&wqkvr,  g_wqkvr);
    cudaGetSymbolAddress((void**)&wgater, g_wgater);
    cudaGetSymbolAddress((void**)&woutr,  g_woutr);
    cudaGetSymbolAddress((void**)&rtab,   g_rope);

    // 0) fused tf32 pre-round + RoPE table (launch #1)
    fused_round_kernel<<<(RNALL + 255) / 256, 256>>>(
        x, xr, Wqkv, wqkvr, Wgate, wgater, Wout, woutr, rtab);

    size_t gemm_smem = (size_t)(GST * BM * BKP + GST * BK * BNP) * sizeof(float);
    cudaFuncSetAttribute(mm_tf32_kernel,
                         cudaFuncAttributeMaxDynamicSharedMemorySize, (int)gemm_smem);

    // 1) QKV GEMM (launch #2)
    mm_tf32_kernel<<<dim3(QKVN / BN, MROWS / BM), 256, gemm_smem>>>(
        xr, wqkvr, qkv, MROWS, QKVN, DMOD, 0, nullptr, nullptr);

    // 2) RMSNorm + RoPE + permute (launch #3)
    norm_rope_kernel<<<BATCH * NHEAD * TSEQ, 128>>>(qkv, rtab, q, k, v);

    // 3) Flash attention (launch #4 -> ncu target)
    size_t fl_smem = (size_t)FSM_FLOATS * sizeof(float);
    cudaFuncSetAttribute(flash_mma_kernel,
                         cudaFuncAttributeMaxDynamicSharedMemorySize, (int)fl_smem);
    flash_mma_kernel<<<dim3(TSEQ / ABR, BATCH * NHEAD), 256, fl_smem>>>(q, k, v, o);

    // 4) gate GEMM with fused sigmoid * attn epilogue (launch #5)
    mm_tf32_kernel<<<dim3(DMOD / BN, MROWS / BM), 256, gemm_smem>>>(
        xr, wgater, g, MROWS, DMOD, DMOD, 1, bgate, o);

    // 5) output GEMM (launch #6)
    mm_tf32_kernel<<<dim3(DMOD / BN, MROWS / BM), 256, gemm_smem>>>(
        g, woutr, out, MROWS, DMOD, DMOD, 0, nullptr, nullptr);
}